// round 1
// baseline (speedup 1.0000x reference)
#include <cuda_runtime.h>

#define NN 50000
#define EE 800000
#define D  128
#define L  3

// ---------------- scratch (device globals; no allocation APIs) ----------------
__device__ float g_x [NN * D];
__device__ float g_h [NN * D];
__device__ float g_h2[NN * D];
__device__ int   g_deg[NN];
__device__ int   g_off[NN + 1];
__device__ int   g_cur[NN];
__device__ int   g_part[256];
__device__ int   g_csr[EE];          // packed: src | (edge_type << 17)
__device__ float g_sum[D];
__device__ float g_ss [D];

__device__ __forceinline__ float* bufsel(int s) {
    return s == 0 ? g_x : (s == 1 ? g_h : g_h2);
}

// ---------------- CSR build ----------------
__global__ void k_zero_deg(int n) {
    int i = blockIdx.x * blockDim.x + threadIdx.x;
    if (i < n) g_deg[i] = 0;
}

__global__ void k_hist(const int* __restrict__ ei, int E) {
    int e = blockIdx.x * blockDim.x + threadIdx.x;
    if (e < E) atomicAdd(&g_deg[ei[E + e]], 1);
}

__global__ void k_scan_partial(int n) {
    __shared__ int sh[256];
    int t = threadIdx.x;
    int i = blockIdx.x * 256 + t;
    sh[t] = (i < n) ? g_deg[i] : 0;
    __syncthreads();
    for (int s = 128; s > 0; s >>= 1) {
        if (t < s) sh[t] += sh[t + s];
        __syncthreads();
    }
    if (t == 0) g_part[blockIdx.x] = sh[0];
}

__global__ void k_scan_part(int nb) {   // 1 block, 256 threads; converts g_part to exclusive
    __shared__ int sh[256];
    int t = threadIdx.x;
    sh[t] = (t < nb) ? g_part[t] : 0;
    __syncthreads();
    for (int o = 1; o < 256; o <<= 1) {
        int v = (t >= o) ? sh[t - o] : 0;
        __syncthreads();
        sh[t] += v;
        __syncthreads();
    }
    if (t < nb) g_part[t] = (t == 0) ? 0 : sh[t - 1];
}

__global__ void k_scan_write(int n) {
    __shared__ int sh[256];
    int t = threadIdx.x;
    int i = blockIdx.x * 256 + t;
    int orig = (i < n) ? g_deg[i] : 0;
    sh[t] = orig;
    __syncthreads();
    for (int o = 1; o < 256; o <<= 1) {
        int v = (t >= o) ? sh[t - o] : 0;
        __syncthreads();
        sh[t] += v;
        __syncthreads();
    }
    if (i < n) g_off[i] = g_part[blockIdx.x] + sh[t] - orig;   // exclusive
}

__global__ void k_copy_cur(int n, int E) {
    int i = blockIdx.x * blockDim.x + threadIdx.x;
    if (i < n) g_cur[i] = g_off[i];
    if (i == 0) g_off[n] = E;
}

__global__ void k_fill(const int* __restrict__ ei, const int* __restrict__ et, int E) {
    int e = blockIdx.x * blockDim.x + threadIdx.x;
    if (e >= E) return;
    int src = ei[e];
    int dst = ei[E + e];
    int p = atomicAdd(&g_cur[dst], 1);
    g_csr[p] = src | (et[e] << 17);
}

// ---------------- feature encoder ----------------
__global__ void k_embed(const int* __restrict__ nt, const float* __restrict__ nemb, int n) {
    int i = blockIdx.x * blockDim.x + threadIdx.x;
    if (i >= n * D) return;
    int node = i >> 7;
    int f = i & 127;
    g_x[i] = nemb[nt[node] * D + f];
}

// ---------------- GINE aggregate + combine:  h = (1+eps)*x + sum relu(x[src]+e) ----------------
__global__ void __launch_bounds__(128) k_agg(const float* __restrict__ eemb,
                                             const float* __restrict__ epsv, int l) {
    int node = blockIdx.x;
    int f = threadIdx.x;
    __shared__ int sh[128];
    float e0 = eemb[f], e1 = eemb[D + f], e2 = eemb[2 * D + f];
    int s = g_off[node], e = g_off[node + 1];
    float acc = 0.f;
    for (int base = s; base < e; base += 128) {
        int cnt = min(128, e - base);
        if (f < cnt) sh[f] = g_csr[base + f];
        __syncthreads();
        for (int i = 0; i < cnt; i++) {
            int p = sh[i];
            int src = p & 0x1FFFF;
            int ety = p >> 17;
            float ev = (ety == 0) ? e0 : (ety == 1) ? e1 : e2;
            float v = g_x[src * D + f] + ev;
            acc += fmaxf(v, 0.f);
        }
        __syncthreads();
    }
    g_h[node * D + f] = (1.f + epsv[l]) * g_x[node * D + f] + acc;
}

// ---------------- 128x128 fp32 GEMM: C[M,128] = act(A[M,128] @ W[128,128] + bias) ----------------
// Block tile: 64 rows x 128 cols, K chunked by 32. 256 threads, each computes 4x8.
__global__ void __launch_bounds__(256) gemm128(int aSel, int cSel,
                                               const float* __restrict__ W,
                                               const float* __restrict__ bias,
                                               int M, int doRelu) {
    __shared__ float As[64][32];
    __shared__ float Ws[32][128];
    const float* A = bufsel(aSel);
    float* C = bufsel(cSel);

    int tid = threadIdx.x;
    int tx = tid & 15;     // col group: 8 cols
    int ty = tid >> 4;     // row group: 4 rows
    int row0 = blockIdx.x * 64;

    float acc[4][8];
#pragma unroll
    for (int r = 0; r < 4; r++)
#pragma unroll
        for (int c = 0; c < 8; c++) acc[r][c] = 0.f;

    for (int kk = 0; kk < 128; kk += 32) {
        // stage A chunk: 64 rows x 32 cols = 512 float4, 2 per thread
#pragma unroll
        for (int i = 0; i < 2; i++) {
            int idx = tid + i * 256;
            int r = idx >> 3;
            int q = idx & 7;
            float4 v = make_float4(0.f, 0.f, 0.f, 0.f);
            if (row0 + r < M)
                v = *(const float4*)&A[(row0 + r) * D + kk + q * 4];
            *(float4*)&As[r][q * 4] = v;
        }
        // stage W chunk: 32 k-rows x 128 cols = 1024 float4, 4 per thread
#pragma unroll
        for (int i = 0; i < 4; i++) {
            int idx = tid + i * 256;
            int k = idx >> 5;
            int q = idx & 31;
            *(float4*)&Ws[k][q * 4] = *(const float4*)&W[(kk + k) * D + q * 4];
        }
        __syncthreads();

#pragma unroll
        for (int k4 = 0; k4 < 8; k4++) {
            float4 a[4];
#pragma unroll
            for (int r = 0; r < 4; r++)
                a[r] = *(float4*)&As[ty * 4 + r][k4 * 4];
#pragma unroll
            for (int k2 = 0; k2 < 4; k2++) {
                float4 w0 = *(float4*)&Ws[k4 * 4 + k2][tx * 8];
                float4 w1 = *(float4*)&Ws[k4 * 4 + k2][tx * 8 + 4];
#pragma unroll
                for (int r = 0; r < 4; r++) {
                    float av = (k2 == 0) ? a[r].x : (k2 == 1) ? a[r].y
                             : (k2 == 2) ? a[r].z : a[r].w;
                    acc[r][0] += av * w0.x; acc[r][1] += av * w0.y;
                    acc[r][2] += av * w0.z; acc[r][3] += av * w0.w;
                    acc[r][4] += av * w1.x; acc[r][5] += av * w1.y;
                    acc[r][6] += av * w1.z; acc[r][7] += av * w1.w;
                }
            }
        }
        __syncthreads();
    }

#pragma unroll
    for (int r = 0; r < 4; r++) {
        int row = row0 + ty * 4 + r;
        if (row < M) {
#pragma unroll
            for (int c4 = 0; c4 < 2; c4++) {
                int c0 = tx * 8 + c4 * 4;
                float4 o;
                o.x = acc[r][c4 * 4 + 0] + bias[c0 + 0];
                o.y = acc[r][c4 * 4 + 1] + bias[c0 + 1];
                o.z = acc[r][c4 * 4 + 2] + bias[c0 + 2];
                o.w = acc[r][c4 * 4 + 3] + bias[c0 + 3];
                if (doRelu) {
                    o.x = fmaxf(o.x, 0.f); o.y = fmaxf(o.y, 0.f);
                    o.z = fmaxf(o.z, 0.f); o.w = fmaxf(o.w, 0.f);
                }
                *(float4*)&C[row * D + c0] = o;
            }
        }
    }
}

// ---------------- BatchNorm ----------------
__global__ void k_zero_stats() {
    int f = threadIdx.x;
    g_sum[f] = 0.f;
    g_ss[f] = 0.f;
}

__global__ void __launch_bounds__(128) k_bn_stats(int M) {
    int f = threadIdx.x;
    float s = 0.f, ss = 0.f;
    for (int r = blockIdx.x; r < M; r += gridDim.x) {
        float v = g_h[r * D + f];
        s += v;
        ss += v * v;
    }
    atomicAdd(&g_sum[f], s);
    atomicAdd(&g_ss[f], ss);
}

__global__ void k_bn_apply(const float* __restrict__ gamma,
                           const float* __restrict__ beta, int M) {
    int i = blockIdx.x * blockDim.x + threadIdx.x;
    if (i >= M * D) return;
    int f = i & 127;
    float mu = g_sum[f] / (float)M;
    float var = g_ss[f] / (float)M - mu * mu;
    float v = (g_h[i] - mu) * rsqrtf(var + 1e-5f) * gamma[f] + beta[f];
    g_x[i] = fmaxf(v, 0.f);
}

// ---------------- head final dot:  out[n] = h2[n,:] . w + b ----------------
__global__ void k_head3(const float* __restrict__ w3, const float* __restrict__ b3,
                        float* __restrict__ out, int M) {
    int gwarp = (blockIdx.x * blockDim.x + threadIdx.x) >> 5;
    int lane = threadIdx.x & 31;
    if (gwarp >= M) return;
    float4 a = *(const float4*)&g_h2[gwarp * D + lane * 4];
    float4 w = *(const float4*)&w3[lane * 4];
    float s = a.x * w.x + a.y * w.y + a.z * w.z + a.w * w.w;
#pragma unroll
    for (int o = 16; o > 0; o >>= 1)
        s += __shfl_down_sync(0xFFFFFFFFu, s, o);
    if (lane == 0) out[gwarp] = s + b3[0];
}

// ---------------- launcher ----------------
extern "C" void kernel_launch(void* const* d_in, const int* in_sizes, int n_in,
                              void* d_out, int out_size) {
    const int*   node_type  = (const int*)  d_in[0];
    const int*   edge_type  = (const int*)  d_in[1];
    const int*   edge_index = (const int*)  d_in[2];
    const float* node_emb   = (const float*)d_in[3];
    const float* edge_emb   = (const float*)d_in[4];
    const float* eps        = (const float*)d_in[5];
    const float* W1         = (const float*)d_in[6];
    const float* b1         = (const float*)d_in[7];
    const float* W2         = (const float*)d_in[8];
    const float* b2         = (const float*)d_in[9];
    const float* gamma      = (const float*)d_in[10];
    const float* beta       = (const float*)d_in[11];
    const float* hW1        = (const float*)d_in[12];
    const float* hb1        = (const float*)d_in[13];
    const float* hW2        = (const float*)d_in[14];
    const float* hb2        = (const float*)d_in[15];
    const float* hW3        = (const float*)d_in[16];
    const float* hb3        = (const float*)d_in[17];
    float* out = (float*)d_out;

    int N = in_sizes[0];
    int E = in_sizes[1];
    int nb = (N + 255) / 256;

    // CSR build (counting sort by dst)
    k_zero_deg<<<nb, 256>>>(N);
    k_hist<<<(E + 255) / 256, 256>>>(edge_index, E);
    k_scan_partial<<<nb, 256>>>(N);
    k_scan_part<<<1, 256>>>(nb);
    k_scan_write<<<nb, 256>>>(N);
    k_copy_cur<<<nb, 256>>>(N, E);
    k_fill<<<(E + 255) / 256, 256>>>(edge_index, edge_type, E);

    // feature encoder
    k_embed<<<(N * D + 255) / 256, 256>>>(node_type, node_emb, N);

    // GINE layers
    for (int l = 0; l < L; l++) {
        k_agg<<<N, 128>>>(edge_emb, eps, l);                           // x -> h
        gemm128<<<(N + 63) / 64, 256>>>(1, 2, W1 + l * D * D, b1 + l * D, N, 1); // h -> h2 (relu)
        gemm128<<<(N + 63) / 64, 256>>>(2, 1, W2 + l * D * D, b2 + l * D, N, 0); // h2 -> h
        k_zero_stats<<<1, 128>>>();
        k_bn_stats<<<256, 128>>>(N);
        k_bn_apply<<<(N * D + 255) / 256, 256>>>(gamma + l * D, beta + l * D, N); // h -> x (relu)
    }

    // head MLP
    gemm128<<<(N + 63) / 64, 256>>>(0, 1, hW1, hb1, N, 1);  // x  -> h  (relu)
    gemm128<<<(N + 63) / 64, 256>>>(1, 2, hW2, hb2, N, 1);  // h  -> h2 (relu)
    k_head3<<<(N + 7) / 8, 256>>>(hW3, hb3, out, N);
}

// round 3
// speedup vs baseline: 1.2393x; 1.2393x over previous
#include <cuda_runtime.h>
#include <cstdint>

#define NN 50000
#define EE 800000
#define D  128
#define L  3

// ---------------- scratch (device globals; no allocation APIs) ----------------
__device__ float g_x [NN * D];
__device__ float g_h [NN * D];
__device__ float g_h2[NN * D];
__device__ int   g_deg[NN];
__device__ int   g_off[NN + 1];
__device__ int   g_cur[NN];
__device__ int   g_part[256];
__device__ int   g_csr[EE];             // packed: src | (edge_type << 17)
__device__ float g_sum[D];
__device__ float g_ss [D];

__device__ __forceinline__ float* bufsel(int s) {
    return s == 0 ? g_x : (s == 1 ? g_h : g_h2);
}

// ---------------- CSR build ----------------
__global__ void k_zero_deg(int n) {
    int i = blockIdx.x * blockDim.x + threadIdx.x;
    if (i < n) g_deg[i] = 0;
}
__global__ void k_hist(const int* __restrict__ ei, int E) {
    int e = blockIdx.x * blockDim.x + threadIdx.x;
    if (e < E) atomicAdd(&g_deg[ei[E + e]], 1);
}
__global__ void k_scan_partial(int n) {
    __shared__ int sh[256];
    int t = threadIdx.x;
    int i = blockIdx.x * 256 + t;
    sh[t] = (i < n) ? g_deg[i] : 0;
    __syncthreads();
    for (int s = 128; s > 0; s >>= 1) { if (t < s) sh[t] += sh[t + s]; __syncthreads(); }
    if (t == 0) g_part[blockIdx.x] = sh[0];
}
__global__ void k_scan_part(int nb) {
    __shared__ int sh[256];
    int t = threadIdx.x;
    sh[t] = (t < nb) ? g_part[t] : 0;
    __syncthreads();
    for (int o = 1; o < 256; o <<= 1) {
        int v = (t >= o) ? sh[t - o] : 0;
        __syncthreads(); sh[t] += v; __syncthreads();
    }
    if (t < nb) g_part[t] = (t == 0) ? 0 : sh[t - 1];
}
__global__ void k_scan_write(int n) {
    __shared__ int sh[256];
    int t = threadIdx.x;
    int i = blockIdx.x * 256 + t;
    int orig = (i < n) ? g_deg[i] : 0;
    sh[t] = orig;
    __syncthreads();
    for (int o = 1; o < 256; o <<= 1) {
        int v = (t >= o) ? sh[t - o] : 0;
        __syncthreads(); sh[t] += v; __syncthreads();
    }
    if (i < n) g_off[i] = g_part[blockIdx.x] + sh[t] - orig;
}
__global__ void k_copy_cur(int n, int E) {
    int i = blockIdx.x * blockDim.x + threadIdx.x;
    if (i < n) g_cur[i] = g_off[i];
    if (i == 0) g_off[n] = E;
}
__global__ void k_fill(const int* __restrict__ ei, const int* __restrict__ et, int E) {
    int e = blockIdx.x * blockDim.x + threadIdx.x;
    if (e >= E) return;
    int dst = ei[E + e];
    int p = atomicAdd(&g_cur[dst], 1);
    g_csr[p] = ei[e] | (et[e] << 17);
}

// ---------------- feature encoder ----------------
__global__ void k_embed(const int* __restrict__ nt, const float* __restrict__ nemb, int n) {
    int i = blockIdx.x * blockDim.x + threadIdx.x;
    if (i >= n * D) return;
    g_x[i] = nemb[nt[i >> 7] * D + (i & 127)];
}

// ---------------- GINE aggregate: warp per node, float4 per lane ----------------
__global__ void __launch_bounds__(128) k_agg(const float* __restrict__ eemb,
                                             const float* __restrict__ epsv, int l, int n) {
    int warp = (blockIdx.x * 128 + threadIdx.x) >> 5;
    int lane = threadIdx.x & 31;
    if (warp >= n) return;
    int node = warp;
    float4 e0 = *(const float4*)&eemb[lane * 4];
    float4 e1 = *(const float4*)&eemb[D + lane * 4];
    float4 e2 = *(const float4*)&eemb[2 * D + lane * 4];
    int s = g_off[node], e = g_off[node + 1];
    float4 acc = make_float4(0.f, 0.f, 0.f, 0.f);
    for (int base = s; base < e; base += 32) {
        int cnt = min(32, e - base);
        int p = (lane < cnt) ? g_csr[base + lane] : 0;
        for (int j = 0; j < cnt; j++) {
            int pj = __shfl_sync(0xFFFFFFFFu, p, j);
            int src = pj & 0x1FFFF;
            int ety = pj >> 17;
            float4 ev = (ety == 0) ? e0 : (ety == 1) ? e1 : e2;
            float4 v = *(const float4*)&g_x[src * D + lane * 4];
            acc.x += fmaxf(v.x + ev.x, 0.f);
            acc.y += fmaxf(v.y + ev.y, 0.f);
            acc.z += fmaxf(v.z + ev.z, 0.f);
            acc.w += fmaxf(v.w + ev.w, 0.f);
        }
    }
    float ep = 1.f + epsv[l];
    float4 xm = *(const float4*)&g_x[node * D + lane * 4];
    float4 o;
    o.x = ep * xm.x + acc.x; o.y = ep * xm.y + acc.y;
    o.z = ep * xm.z + acc.z; o.w = ep * xm.w + acc.w;
    *(float4*)&g_h[node * D + lane * 4] = o;
}

// ---------------- tensor-core GEMM (mma.sync tf32, 3xTF32 compensated) ----------------
// C[M,128] = act(A[M,128] @ W[128,128] + bias).  Block tile: 128 rows.
// 8 warps: wr = wid&3 -> 32-row group, wc = wid>>2 -> 64-col group.
// A staged [128][132] (bank-conflict-free frag loads), W staged [k][n] at [128][136].
#define SSA 132
#define SSW 136
#define GEMM_SMEM ((128 * SSA + 128 * SSW) * 4)

__device__ __forceinline__ void tf32_split(float v, uint32_t& hi, uint32_t& lo) {
    uint32_t h;
    asm("cvt.rna.tf32.f32 %0, %1;" : "=r"(h) : "f"(v));
    float r = v - __uint_as_float(h);
    uint32_t l;
    asm("cvt.rna.tf32.f32 %0, %1;" : "=r"(l) : "f"(r));
    hi = h; lo = l;
}

__device__ __forceinline__ void mma8(float* c, const uint32_t* a, const uint32_t* b) {
    asm volatile("mma.sync.aligned.m16n8k8.row.col.f32.tf32.tf32.f32 "
                 "{%0,%1,%2,%3}, {%4,%5,%6,%7}, {%8,%9}, {%0,%1,%2,%3};"
                 : "+f"(c[0]), "+f"(c[1]), "+f"(c[2]), "+f"(c[3])
                 : "r"(a[0]), "r"(a[1]), "r"(a[2]), "r"(a[3]), "r"(b[0]), "r"(b[1]));
}

__global__ void __launch_bounds__(256, 1) k_gemm_tc(int aSel, int cSel,
                                                    const float* __restrict__ W,
                                                    const float* __restrict__ bias,
                                                    int M, int doRelu) {
    extern __shared__ float sm[];
    float* As = sm;                 // [128][SSA]
    float* Ws = sm + 128 * SSA;     // [128][SSW], layout [k][n]
    const float* A = bufsel(aSel);
    float* C = bufsel(cSel);

    int tid = threadIdx.x;
    int wid = tid >> 5;
    int lane = tid & 31;
    int row0 = blockIdx.x * 128;

    // stage A: 128 x 128 floats (zero-pad past M)
    for (int i = tid; i < 4096; i += 256) {
        int r = i >> 5, q = i & 31;
        int gr = row0 + r;
        float4 v = make_float4(0.f, 0.f, 0.f, 0.f);
        if (gr < M) v = *(const float4*)&A[(size_t)gr * D + q * 4];
        *(float4*)&As[r * SSA + q * 4] = v;
    }
    // stage W: direct copy, [k][n]
    for (int i = tid; i < 4096; i += 256) {
        int kr = i >> 5, q = i & 31;
        float4 v = *(const float4*)&W[kr * D + q * 4];
        *(float4*)&Ws[kr * SSW + q * 4] = v;
    }
    __syncthreads();

    const int wr = (wid & 3) * 32;   // row group base
    const int wc = (wid >> 2) * 64;  // col group base
    const int lr = lane >> 2;        // 0..7
    const int lc = lane & 3;         // 0..3

    float acc[2][8][4];
#pragma unroll
    for (int m = 0; m < 2; m++)
#pragma unroll
        for (int n = 0; n < 8; n++)
#pragma unroll
            for (int q = 0; q < 4; q++) acc[m][n][q] = 0.f;

#pragma unroll
    for (int k0 = 0; k0 < 128; k0 += 8) {
        uint32_t ah[2][4], al[2][4];
#pragma unroll
        for (int m = 0; m < 2; m++) {
            int r = wr + m * 16 + lr;
            float v0 = As[r * SSA + k0 + lc];
            float v1 = As[(r + 8) * SSA + k0 + lc];
            float v2 = As[r * SSA + k0 + lc + 4];
            float v3 = As[(r + 8) * SSA + k0 + lc + 4];
            tf32_split(v0, ah[m][0], al[m][0]);
            tf32_split(v1, ah[m][1], al[m][1]);
            tf32_split(v2, ah[m][2], al[m][2]);
            tf32_split(v3, ah[m][3], al[m][3]);
        }
        uint32_t bh[8][2], bl[8][2];
#pragma unroll
        for (int n = 0; n < 8; n++) {
            int col = wc + n * 8 + lr;
            float v0 = Ws[(k0 + lc) * SSW + col];
            float v1 = Ws[(k0 + lc + 4) * SSW + col];
            tf32_split(v0, bh[n][0], bl[n][0]);
            tf32_split(v1, bh[n][1], bl[n][1]);
        }
#pragma unroll
        for (int m = 0; m < 2; m++)
#pragma unroll
            for (int n = 0; n < 8; n++) {
                mma8(acc[m][n], ah[m], bh[n]);
                mma8(acc[m][n], ah[m], bl[n]);
                mma8(acc[m][n], al[m], bh[n]);
            }
    }

    // epilogue: bias + optional relu, float2 stores
#pragma unroll
    for (int m = 0; m < 2; m++) {
        int row = row0 + wr + m * 16 + lr;
#pragma unroll
        for (int n = 0; n < 8; n++) {
            int col = wc + n * 8 + lc * 2;
            float bx = bias[col], by = bias[col + 1];
            if (row < M) {
                float2 o;
                o.x = acc[m][n][0] + bx;
                o.y = acc[m][n][1] + by;
                if (doRelu) { o.x = fmaxf(o.x, 0.f); o.y = fmaxf(o.y, 0.f); }
                *(float2*)&C[(size_t)row * D + col] = o;
            }
            if (row + 8 < M) {
                float2 o;
                o.x = acc[m][n][2] + bx;
                o.y = acc[m][n][3] + by;
                if (doRelu) { o.x = fmaxf(o.x, 0.f); o.y = fmaxf(o.y, 0.f); }
                *(float2*)&C[(size_t)(row + 8) * D + col] = o;
            }
        }
    }
}

// ---------------- BatchNorm ----------------
__global__ void k_zero_stats() {
    int f = threadIdx.x;
    g_sum[f] = 0.f;
    g_ss[f] = 0.f;
}
__global__ void __launch_bounds__(128) k_bn_stats(int M) {
    int f = threadIdx.x;
    float s = 0.f, ss = 0.f;
    for (int r = blockIdx.x; r < M; r += gridDim.x) {
        float v = g_h[r * D + f];
        s += v; ss += v * v;
    }
    atomicAdd(&g_sum[f], s);
    atomicAdd(&g_ss[f], ss);
}
__global__ void k_bn_apply(const float* __restrict__ gamma,
                           const float* __restrict__ beta, int M) {
    int i = blockIdx.x * blockDim.x + threadIdx.x;
    if (i >= M * D) return;
    int f = i & 127;
    float mu = g_sum[f] / (float)M;
    float var = g_ss[f] / (float)M - mu * mu;
    float v = (g_h[i] - mu) * rsqrtf(var + 1e-5f) * gamma[f] + beta[f];
    g_x[i] = fmaxf(v, 0.f);
}

// ---------------- head final dot ----------------
__global__ void k_head3(const float* __restrict__ w3, const float* __restrict__ b3,
                        float* __restrict__ out, int M) {
    int gwarp = (blockIdx.x * blockDim.x + threadIdx.x) >> 5;
    int lane = threadIdx.x & 31;
    if (gwarp >= M) return;
    float4 a = *(const float4*)&g_h2[gwarp * D + lane * 4];
    float4 w = *(const float4*)&w3[lane * 4];
    float s = a.x * w.x + a.y * w.y + a.z * w.z + a.w * w.w;
#pragma unroll
    for (int o = 16; o > 0; o >>= 1)
        s += __shfl_down_sync(0xFFFFFFFFu, s, o);
    if (lane == 0) out[gwarp] = s + b3[0];
}

// ---------------- launcher ----------------
extern "C" void kernel_launch(void* const* d_in, const int* in_sizes, int n_in,
                              void* d_out, int out_size) {
    const int*   node_type  = (const int*)  d_in[0];
    const int*   edge_type  = (const int*)  d_in[1];
    const int*   edge_index = (const int*)  d_in[2];
    const float* node_emb   = (const float*)d_in[3];
    const float* edge_emb   = (const float*)d_in[4];
    const float* eps        = (const float*)d_in[5];
    const float* W1         = (const float*)d_in[6];
    const float* b1         = (const float*)d_in[7];
    const float* W2         = (const float*)d_in[8];
    const float* b2         = (const float*)d_in[9];
    const float* gamma      = (const float*)d_in[10];
    const float* beta       = (const float*)d_in[11];
    const float* hW1        = (const float*)d_in[12];
    const float* hb1        = (const float*)d_in[13];
    const float* hW2        = (const float*)d_in[14];
    const float* hb2        = (const float*)d_in[15];
    const float* hW3        = (const float*)d_in[16];
    const float* hb3        = (const float*)d_in[17];
    float* out = (float*)d_out;

    int N = in_sizes[0];
    int E = in_sizes[1];
    int nb = (N + 255) / 256;
    int gTiles = (N + 127) / 128;

    static int smemSet = 0;
    if (!smemSet) {
        cudaFuncSetAttribute(k_gemm_tc, cudaFuncAttributeMaxDynamicSharedMemorySize, GEMM_SMEM);
        smemSet = 1;
    }

    // CSR build (counting sort by dst)
    k_zero_deg<<<nb, 256>>>(N);
    k_hist<<<(E + 255) / 256, 256>>>(edge_index, E);
    k_scan_partial<<<nb, 256>>>(N);
    k_scan_part<<<1, 256>>>(nb);
    k_scan_write<<<nb, 256>>>(N);
    k_copy_cur<<<nb, 256>>>(N, E);
    k_fill<<<(E + 255) / 256, 256>>>(edge_index, edge_type, E);

    // feature encoder
    k_embed<<<(N * D + 255) / 256, 256>>>(node_type, node_emb, N);

    // GINE layers
    for (int l = 0; l < L; l++) {
        k_agg<<<(N + 3) / 4, 128>>>(edge_emb, eps, l, N);                         // x -> h
        k_gemm_tc<<<gTiles, 256, GEMM_SMEM>>>(1, 2, W1 + l * D * D, b1 + l * D, N, 1); // h -> h2 (relu)
        k_gemm_tc<<<gTiles, 256, GEMM_SMEM>>>(2, 1, W2 + l * D * D, b2 + l * D, N, 0); // h2 -> h
        k_zero_stats<<<1, 128>>>();
        k_bn_stats<<<256, 128>>>(N);
        k_bn_apply<<<(N * D + 255) / 256, 256>>>(gamma + l * D, beta + l * D, N); // h -> x (relu)
    }

    // head MLP
    k_gemm_tc<<<gTiles, 256, GEMM_SMEM>>>(0, 1, hW1, hb1, N, 1);   // x  -> h  (relu)
    k_gemm_tc<<<gTiles, 256, GEMM_SMEM>>>(1, 2, hW2, hb2, N, 1);   // h  -> h2 (relu)
    k_head3<<<(N + 7) / 8, 256>>>(hW3, hb3, out, N);
}

// round 5
// speedup vs baseline: 1.6040x; 1.2942x over previous
#include <cuda_runtime.h>
#include <cstdint>

#define NN 50000
#define EE 800000
#define D  128
#define L  3

// ---------------- scratch (device globals; no allocation APIs) ----------------
__device__ float g_x [NN * D];
__device__ float g_h [NN * D];
__device__ float g_h2[NN * D];
__device__ int   g_deg[NN];
__device__ int   g_off[NN + 1];
__device__ int   g_cur[NN];
__device__ int   g_csr[EE];             // packed: src | (edge_type << 17)
__device__ float g_sum[D];
__device__ float g_ss [D];

__device__ __forceinline__ float* bufsel(int s) {
    return s == 0 ? g_x : (s == 1 ? g_h : g_h2);
}

// ---------------- CSR build ----------------
__global__ void k_zero_deg(int n) {
    int i = blockIdx.x * blockDim.x + threadIdx.x;
    if (i < n) g_deg[i] = 0;
}
__global__ void k_hist(const int* __restrict__ ei, int E) {
    int e = blockIdx.x * blockDim.x + threadIdx.x;
    if (e < E) atomicAdd(&g_deg[ei[E + e]], 1);
}

// single-block exclusive scan over g_deg -> g_off, g_cur (warp-shuffle based)
__global__ void __launch_bounds__(1024) k_scan1(int n, int E) {
    __shared__ int wsum[32];
    __shared__ int wpre[32];
    __shared__ int stot;
    int t = threadIdx.x;
    int lane = t & 31;
    int w = t >> 5;
    int run = 0;
    for (int base = 0; base < n; base += 1024) {
        int i = base + t;
        int v = (i < n) ? g_deg[i] : 0;
        // warp inclusive scan
        int s = v;
#pragma unroll
        for (int o = 1; o < 32; o <<= 1) {
            int x = __shfl_up_sync(0xFFFFFFFFu, s, o);
            if (lane >= o) s += x;
        }
        if (lane == 31) wsum[w] = s;
        __syncthreads();
        if (w == 0) {
            int x = wsum[lane];
            int ss = x;
#pragma unroll
            for (int o = 1; o < 32; o <<= 1) {
                int y = __shfl_up_sync(0xFFFFFFFFu, ss, o);
                if (lane >= o) ss += y;
            }
            wpre[lane] = ss - x;
            if (lane == 31) stot = ss;
        }
        __syncthreads();
        int excl = run + wpre[w] + s - v;
        if (i < n) { g_off[i] = excl; g_cur[i] = excl; }
        run += stot;
        __syncthreads();
    }
    if (t == 0) g_off[n] = E;
}

__global__ void k_fill(const int* __restrict__ ei, const int* __restrict__ et, int E) {
    int e = blockIdx.x * blockDim.x + threadIdx.x;
    if (e >= E) return;
    int dst = ei[E + e];
    int p = atomicAdd(&g_cur[dst], 1);
    g_csr[p] = ei[e] | (et[e] << 17);
}

// ---------------- feature encoder ----------------
__global__ void k_embed(const int* __restrict__ nt, const float* __restrict__ nemb, int n) {
    int i = blockIdx.x * blockDim.x + threadIdx.x;
    if (i >= n * D) return;
    g_x[i] = nemb[nt[i >> 7] * D + (i & 127)];
}

// ---------------- GINE aggregate: warp per node, float4 per lane, 2-way unroll ----------------
// Block 0 also zeroes the BN stats accumulators for this layer.
__global__ void __launch_bounds__(256) k_agg(const float* __restrict__ eemb,
                                             const float* __restrict__ epsv, int l, int n) {
    if (blockIdx.x == 0 && threadIdx.x < D) {
        g_sum[threadIdx.x] = 0.f;
        g_ss[threadIdx.x] = 0.f;
    }
    int warp = (blockIdx.x * 256 + threadIdx.x) >> 5;
    int lane = threadIdx.x & 31;
    if (warp >= n) return;
    int node = warp;
    float4 e0 = *(const float4*)&eemb[lane * 4];
    float4 e1 = *(const float4*)&eemb[D + lane * 4];
    float4 e2 = *(const float4*)&eemb[2 * D + lane * 4];
    int s = g_off[node], e = g_off[node + 1];
    float4 acc  = make_float4(0.f, 0.f, 0.f, 0.f);
    float4 acc2 = make_float4(0.f, 0.f, 0.f, 0.f);
    for (int base = s; base < e; base += 32) {
        int cnt = min(32, e - base);
        int p = (lane < cnt) ? g_csr[base + lane] : 0;
        int j = 0;
        for (; j + 1 < cnt; j += 2) {
            int pj0 = __shfl_sync(0xFFFFFFFFu, p, j);
            int pj1 = __shfl_sync(0xFFFFFFFFu, p, j + 1);
            float4 v0 = *(const float4*)&g_x[(size_t)(pj0 & 0x1FFFF) * D + lane * 4];
            float4 v1 = *(const float4*)&g_x[(size_t)(pj1 & 0x1FFFF) * D + lane * 4];
            int t0 = pj0 >> 17, t1 = pj1 >> 17;
            float4 ev0 = (t0 == 0) ? e0 : (t0 == 1) ? e1 : e2;
            float4 ev1 = (t1 == 0) ? e0 : (t1 == 1) ? e1 : e2;
            acc.x  += fmaxf(v0.x + ev0.x, 0.f);
            acc.y  += fmaxf(v0.y + ev0.y, 0.f);
            acc.z  += fmaxf(v0.z + ev0.z, 0.f);
            acc.w  += fmaxf(v0.w + ev0.w, 0.f);
            acc2.x += fmaxf(v1.x + ev1.x, 0.f);
            acc2.y += fmaxf(v1.y + ev1.y, 0.f);
            acc2.z += fmaxf(v1.z + ev1.z, 0.f);
            acc2.w += fmaxf(v1.w + ev1.w, 0.f);
        }
        if (j < cnt) {
            int pj0 = __shfl_sync(0xFFFFFFFFu, p, j);
            float4 v0 = *(const float4*)&g_x[(size_t)(pj0 & 0x1FFFF) * D + lane * 4];
            int t0 = pj0 >> 17;
            float4 ev0 = (t0 == 0) ? e0 : (t0 == 1) ? e1 : e2;
            acc.x += fmaxf(v0.x + ev0.x, 0.f);
            acc.y += fmaxf(v0.y + ev0.y, 0.f);
            acc.z += fmaxf(v0.z + ev0.z, 0.f);
            acc.w += fmaxf(v0.w + ev0.w, 0.f);
        }
    }
    float ep = 1.f + epsv[l];
    float4 xm = *(const float4*)&g_x[(size_t)node * D + lane * 4];
    float4 o;
    o.x = ep * xm.x + acc.x + acc2.x;
    o.y = ep * xm.y + acc.y + acc2.y;
    o.z = ep * xm.z + acc.z + acc2.z;
    o.w = ep * xm.w + acc.w + acc2.w;
    *(float4*)&g_h[(size_t)node * D + lane * 4] = o;
}

// ---------------- tensor-core GEMM (mma.sync tf32, 3xTF32 compensated) ----------------
// C[M,128] = act(A[M,128] @ W[128,128] + bias).  Block tile: 64 rows (2 CTAs/SM).
// 8 warps: wr = (wid&1)*32 rows, wc = (wid>>1)*32 cols; per warp 2 m-tiles x 4 n-tiles.
// Optional fused BN statistics (per-column sum / sum-of-squares).
#define SSA 132
#define SSW 136
#define GEMM_SMEM ((64 * SSA + 128 * SSW) * 4)

__device__ __forceinline__ void tf32_split(float v, uint32_t& hi, uint32_t& lo) {
    uint32_t h;
    asm("cvt.rna.tf32.f32 %0, %1;" : "=r"(h) : "f"(v));
    float r = v - __uint_as_float(h);
    uint32_t l;
    asm("cvt.rna.tf32.f32 %0, %1;" : "=r"(l) : "f"(r));
    hi = h; lo = l;
}

__device__ __forceinline__ void mma8(float* c, const uint32_t* a, const uint32_t* b) {
    asm volatile("mma.sync.aligned.m16n8k8.row.col.f32.tf32.tf32.f32 "
                 "{%0,%1,%2,%3}, {%4,%5,%6,%7}, {%8,%9}, {%0,%1,%2,%3};"
                 : "+f"(c[0]), "+f"(c[1]), "+f"(c[2]), "+f"(c[3])
                 : "r"(a[0]), "r"(a[1]), "r"(a[2]), "r"(a[3]), "r"(b[0]), "r"(b[1]));
}

__global__ void __launch_bounds__(256, 2) k_gemm_tc(int aSel, int cSel,
                                                    const float* __restrict__ W,
                                                    const float* __restrict__ bias,
                                                    int M, int doRelu, int doStats) {
    extern __shared__ float sm[];
    float* As = sm;                 // [64][SSA]
    float* Ws = sm + 64 * SSA;      // [128][SSW], layout [k][n]
    const float* A = bufsel(aSel);
    float* C = bufsel(cSel);

    int tid = threadIdx.x;
    int wid = tid >> 5;
    int lane = tid & 31;
    int row0 = blockIdx.x * 64;

    // stage A: 64 x 128 floats (zero-pad past M)
    for (int i = tid; i < 2048; i += 256) {
        int r = i >> 5, q = i & 31;
        int gr = row0 + r;
        float4 v = make_float4(0.f, 0.f, 0.f, 0.f);
        if (gr < M) v = *(const float4*)&A[(size_t)gr * D + q * 4];
        *(float4*)&As[r * SSA + q * 4] = v;
    }
    // stage W: direct copy, [k][n]
    for (int i = tid; i < 4096; i += 256) {
        int kr = i >> 5, q = i & 31;
        float4 v = *(const float4*)&W[kr * D + q * 4];
        *(float4*)&Ws[kr * SSW + q * 4] = v;
    }
    __syncthreads();

    const int wr = (wid & 1) * 32;   // row group base
    const int wc = (wid >> 1) * 32;  // col group base
    const int lr = lane >> 2;        // 0..7
    const int lc = lane & 3;         // 0..3

    float acc[2][4][4];
#pragma unroll
    for (int m = 0; m < 2; m++)
#pragma unroll
        for (int n = 0; n < 4; n++)
#pragma unroll
            for (int q = 0; q < 4; q++) acc[m][n][q] = 0.f;

#pragma unroll
    for (int k0 = 0; k0 < 128; k0 += 8) {
        uint32_t ah[2][4], al[2][4];
#pragma unroll
        for (int m = 0; m < 2; m++) {
            int r = wr + m * 16 + lr;
            float v0 = As[r * SSA + k0 + lc];
            float v1 = As[(r + 8) * SSA + k0 + lc];
            float v2 = As[r * SSA + k0 + lc + 4];
            float v3 = As[(r + 8) * SSA + k0 + lc + 4];
            tf32_split(v0, ah[m][0], al[m][0]);
            tf32_split(v1, ah[m][1], al[m][1]);
            tf32_split(v2, ah[m][2], al[m][2]);
            tf32_split(v3, ah[m][3], al[m][3]);
        }
        uint32_t bh[4][2], bl[4][2];
#pragma unroll
        for (int n = 0; n < 4; n++) {
            int col = wc + n * 8 + lr;
            float v0 = Ws[(k0 + lc) * SSW + col];
            float v1 = Ws[(k0 + lc + 4) * SSW + col];
            tf32_split(v0, bh[n][0], bl[n][0]);
            tf32_split(v1, bh[n][1], bl[n][1]);
        }
#pragma unroll
        for (int m = 0; m < 2; m++)
#pragma unroll
            for (int n = 0; n < 4; n++) {
                mma8(acc[m][n], ah[m], bh[n]);
                mma8(acc[m][n], ah[m], bl[n]);
                mma8(acc[m][n], al[m], bh[n]);
            }
    }

    // epilogue: bias + optional relu, float2 stores; optional fused BN stats
    float ps[4][2], pss[4][2];
#pragma unroll
    for (int n = 0; n < 4; n++)
#pragma unroll
        for (int q = 0; q < 2; q++) { ps[n][q] = 0.f; pss[n][q] = 0.f; }

#pragma unroll
    for (int m = 0; m < 2; m++) {
        int row = row0 + wr + m * 16 + lr;
#pragma unroll
        for (int n = 0; n < 4; n++) {
            int col = wc + n * 8 + lc * 2;
            float bx = bias[col], by = bias[col + 1];
            if (row < M) {
                float ox = acc[m][n][0] + bx;
                float oy = acc[m][n][1] + by;
                if (doStats) {
                    ps[n][0] += ox; pss[n][0] += ox * ox;
                    ps[n][1] += oy; pss[n][1] += oy * oy;
                }
                float2 o;
                o.x = doRelu ? fmaxf(ox, 0.f) : ox;
                o.y = doRelu ? fmaxf(oy, 0.f) : oy;
                *(float2*)&C[(size_t)row * D + col] = o;
            }
            if (row + 8 < M) {
                float ox = acc[m][n][2] + bx;
                float oy = acc[m][n][3] + by;
                if (doStats) {
                    ps[n][0] += ox; pss[n][0] += ox * ox;
                    ps[n][1] += oy; pss[n][1] += oy * oy;
                }
                float2 o;
                o.x = doRelu ? fmaxf(ox, 0.f) : ox;
                o.y = doRelu ? fmaxf(oy, 0.f) : oy;
                *(float2*)&C[(size_t)(row + 8) * D + col] = o;
            }
        }
    }

    if (doStats) {
        // reduce across lanes sharing the same columns (same lc, lr = 0..7)
#pragma unroll
        for (int n = 0; n < 4; n++)
#pragma unroll
            for (int q = 0; q < 2; q++) {
#pragma unroll
                for (int off = 4; off < 32; off <<= 1) {
                    ps[n][q]  += __shfl_xor_sync(0xFFFFFFFFu, ps[n][q], off);
                    pss[n][q] += __shfl_xor_sync(0xFFFFFFFFu, pss[n][q], off);
                }
            }
        if (lr == 0) {
#pragma unroll
            for (int n = 0; n < 4; n++) {
                int col = wc + n * 8 + lc * 2;
                atomicAdd(&g_sum[col], ps[n][0]);
                atomicAdd(&g_sum[col + 1], ps[n][1]);
                atomicAdd(&g_ss[col], pss[n][0]);
                atomicAdd(&g_ss[col + 1], pss[n][1]);
            }
        }
    }
}

// ---------------- BatchNorm apply + relu ----------------
__global__ void k_bn_apply(const float* __restrict__ gamma,
                           const float* __restrict__ beta, int M) {
    int i = blockIdx.x * blockDim.x + threadIdx.x;
    if (i >= M * D) return;
    int f = i & 127;
    float mu = g_sum[f] / (float)M;
    float var = g_ss[f] / (float)M - mu * mu;
    float v = (g_h[i] - mu) * rsqrtf(var + 1e-5f) * gamma[f] + beta[f];
    g_x[i] = fmaxf(v, 0.f);
}

// ---------------- head final dot ----------------
__global__ void k_head3(const float* __restrict__ w3, const float* __restrict__ b3,
                        float* __restrict__ out, int M) {
    int gwarp = (blockIdx.x * blockDim.x + threadIdx.x) >> 5;
    int lane = threadIdx.x & 31;
    if (gwarp >= M) return;
    float4 a = *(const float4*)&g_h2[(size_t)gwarp * D + lane * 4];
    float4 w = *(const float4*)&w3[lane * 4];
    float s = a.x * w.x + a.y * w.y + a.z * w.z + a.w * w.w;
#pragma unroll
    for (int o = 16; o > 0; o >>= 1)
        s += __shfl_down_sync(0xFFFFFFFFu, s, o);
    if (lane == 0) out[gwarp] = s + b3[0];
}

// ---------------- launcher ----------------
extern "C" void kernel_launch(void* const* d_in, const int* in_sizes, int n_in,
                              void* d_out, int out_size) {
    const int*   node_type  = (const int*)  d_in[0];
    const int*   edge_type  = (const int*)  d_in[1];
    const int*   edge_index = (const int*)  d_in[2];
    const float* node_emb   = (const float*)d_in[3];
    const float* edge_emb   = (const float*)d_in[4];
    const float* eps        = (const float*)d_in[5];
    const float* W1         = (const float*)d_in[6];
    const float* b1         = (const float*)d_in[7];
    const float* W2         = (const float*)d_in[8];
    const float* b2         = (const float*)d_in[9];
    const float* gamma      = (const float*)d_in[10];
    const float* beta       = (const float*)d_in[11];
    const float* hW1        = (const float*)d_in[12];
    const float* hb1        = (const float*)d_in[13];
    const float* hW2        = (const float*)d_in[14];
    const float* hb2        = (const float*)d_in[15];
    const float* hW3        = (const float*)d_in[16];
    const float* hb3        = (const float*)d_in[17];
    float* out = (float*)d_out;

    int N = in_sizes[0];
    int E = in_sizes[1];
    int gTiles = (N + 63) / 64;

    static int smemSet = 0;
    if (!smemSet) {
        cudaFuncSetAttribute(k_gemm_tc, cudaFuncAttributeMaxDynamicSharedMemorySize, GEMM_SMEM);
        smemSet = 1;
    }

    // CSR build (counting sort by dst): 4 launches
    k_zero_deg<<<(N + 255) / 256, 256>>>(N);
    k_hist<<<(E + 255) / 256, 256>>>(edge_index, E);
    k_scan1<<<1, 1024>>>(N, E);
    k_fill<<<(E + 255) / 256, 256>>>(edge_index, edge_type, E);

    // feature encoder
    k_embed<<<(N * D + 255) / 256, 256>>>(node_type, node_emb, N);

    // GINE layers: agg (also zeroes stats), gemm1(relu), gemm2(+stats), bn_apply(relu)
    for (int l = 0; l < L; l++) {
        k_agg<<<(N + 7) / 8, 256>>>(edge_emb, eps, l, N);                                 // x -> h
        k_gemm_tc<<<gTiles, 256, GEMM_SMEM>>>(1, 2, W1 + l * D * D, b1 + l * D, N, 1, 0); // h -> h2
        k_gemm_tc<<<gTiles, 256, GEMM_SMEM>>>(2, 1, W2 + l * D * D, b2 + l * D, N, 0, 1); // h2 -> h (+stats)
        k_bn_apply<<<(N * D + 255) / 256, 256>>>(gamma + l * D, beta + l * D, N);         // h -> x
    }

    // head MLP
    k_gemm_tc<<<gTiles, 256, GEMM_SMEM>>>(0, 1, hW1, hb1, N, 1, 0);   // x  -> h
    k_gemm_tc<<<gTiles, 256, GEMM_SMEM>>>(1, 2, hW2, hb2, N, 1, 0);   // h  -> h2
    k_head3<<<(N + 7) / 8, 256>>>(hW3, hb3, out, N);
}

// round 8
// speedup vs baseline: 1.6348x; 1.0192x over previous
#include <cuda_runtime.h>
#include <cstdint>

#define NN 50000
#define EE 800000
#define D  128
#define L  3

// ---------------- scratch (device globals; no allocation APIs) ----------------
__device__ float g_x [NN * D];
__device__ float g_h [NN * D];
__device__ float g_h2[NN * D];
__device__ int   g_deg[NN];
__device__ int   g_off[NN + 1];
__device__ int   g_cur[NN];
__device__ int   g_csr[EE];             // packed: src | (edge_type << 17)
__device__ float g_sum[D];
__device__ float g_ss [D];

__device__ __forceinline__ float* bufsel(int s) {
    return s == 0 ? g_x : (s == 1 ? g_h : g_h2);
}

// ---------------- CSR build ----------------
__global__ void k_zero_deg(int n) {
    int i = blockIdx.x * blockDim.x + threadIdx.x;
    if (i < n) g_deg[i] = 0;
}
__global__ void k_hist(const int* __restrict__ ei, int E) {
    int e = blockIdx.x * blockDim.x + threadIdx.x;
    if (e < E) atomicAdd(&g_deg[ei[E + e]], 1);
}

// single-block exclusive scan over g_deg -> g_off, g_cur (warp-shuffle based)
__global__ void __launch_bounds__(1024) k_scan1(int n, int E) {
    __shared__ int wsum[32];
    __shared__ int wpre[32];
    __shared__ int stot;
    int t = threadIdx.x;
    int lane = t & 31;
    int w = t >> 5;
    int run = 0;
    for (int base = 0; base < n; base += 1024) {
        int i = base + t;
        int v = (i < n) ? g_deg[i] : 0;
        int s = v;
#pragma unroll
        for (int o = 1; o < 32; o <<= 1) {
            int x = __shfl_up_sync(0xFFFFFFFFu, s, o);
            if (lane >= o) s += x;
        }
        if (lane == 31) wsum[w] = s;
        __syncthreads();
        if (w == 0) {
            int x = wsum[lane];
            int ss = x;
#pragma unroll
            for (int o = 1; o < 32; o <<= 1) {
                int y = __shfl_up_sync(0xFFFFFFFFu, ss, o);
                if (lane >= o) ss += y;
            }
            wpre[lane] = ss - x;
            if (lane == 31) stot = ss;
        }
        __syncthreads();
        int excl = run + wpre[w] + s - v;
        if (i < n) { g_off[i] = excl; g_cur[i] = excl; }
        run += stot;
        __syncthreads();
    }
    if (t == 0) g_off[n] = E;
}

__global__ void k_fill(const int* __restrict__ ei, const int* __restrict__ et, int E) {
    int e = blockIdx.x * blockDim.x + threadIdx.x;
    if (e >= E) return;
    int dst = ei[E + e];
    int p = atomicAdd(&g_cur[dst], 1);
    g_csr[p] = ei[e] | (et[e] << 17);
}

// ---------------- feature encoder (writes g_h) ----------------
__global__ void k_embed(const int* __restrict__ nt, const float* __restrict__ nemb, int n) {
    int i = blockIdx.x * blockDim.x + threadIdx.x;
    if (i >= n * D) return;
    g_h[i] = nemb[nt[i >> 7] * D + (i & 127)];
}

// ---------------- GINE aggregate (+ optional fused BN-apply of previous layer) ----------------
// reads g_h (NORM: x = relu(h*s1+s2), else x = h), writes g_x = (1+eps)x + sum relu(x_src + e)
template <int NORM>
__global__ void __launch_bounds__(256) k_agg(const float* __restrict__ eemb,
                                             const float* __restrict__ epsv, int l, int n,
                                             const float* __restrict__ gamma,
                                             const float* __restrict__ beta) {
    int warp = (blockIdx.x * 256 + threadIdx.x) >> 5;
    int lane = threadIdx.x & 31;
    if (warp >= n) return;
    int node = warp;

    float s1[4], s2[4];
    if (NORM) {
        float invM = 1.f / (float)n;
#pragma unroll
        for (int c = 0; c < 4; c++) {
            int f = lane * 4 + c;
            float mu = g_sum[f] * invM;
            float var = g_ss[f] * invM - mu * mu;
            float a = gamma[f] * rsqrtf(var + 1e-5f);
            s1[c] = a;
            s2[c] = beta[f] - mu * a;
        }
    }

    float4 e0 = *(const float4*)&eemb[lane * 4];
    float4 e1 = *(const float4*)&eemb[D + lane * 4];
    float4 e2 = *(const float4*)&eemb[2 * D + lane * 4];
    int s = g_off[node], e = g_off[node + 1];
    float4 acc  = make_float4(0.f, 0.f, 0.f, 0.f);
    float4 acc2 = make_float4(0.f, 0.f, 0.f, 0.f);

#define XFORM(v) do { if (NORM) { \
        v.x = fmaxf(v.x * s1[0] + s2[0], 0.f); \
        v.y = fmaxf(v.y * s1[1] + s2[1], 0.f); \
        v.z = fmaxf(v.z * s1[2] + s2[2], 0.f); \
        v.w = fmaxf(v.w * s1[3] + s2[3], 0.f); } } while (0)

    for (int base = s; base < e; base += 32) {
        int cnt = min(32, e - base);
        int p = (lane < cnt) ? g_csr[base + lane] : 0;
        int j = 0;
        for (; j + 1 < cnt; j += 2) {
            int pj0 = __shfl_sync(0xFFFFFFFFu, p, j);
            int pj1 = __shfl_sync(0xFFFFFFFFu, p, j + 1);
            float4 v0 = *(const float4*)&g_h[(size_t)(pj0 & 0x1FFFF) * D + lane * 4];
            float4 v1 = *(const float4*)&g_h[(size_t)(pj1 & 0x1FFFF) * D + lane * 4];
            XFORM(v0); XFORM(v1);
            int t0 = pj0 >> 17, t1 = pj1 >> 17;
            float4 ev0 = (t0 == 0) ? e0 : (t0 == 1) ? e1 : e2;
            float4 ev1 = (t1 == 0) ? e0 : (t1 == 1) ? e1 : e2;
            acc.x  += fmaxf(v0.x + ev0.x, 0.f);
            acc.y  += fmaxf(v0.y + ev0.y, 0.f);
            acc.z  += fmaxf(v0.z + ev0.z, 0.f);
            acc.w  += fmaxf(v0.w + ev0.w, 0.f);
            acc2.x += fmaxf(v1.x + ev1.x, 0.f);
            acc2.y += fmaxf(v1.y + ev1.y, 0.f);
            acc2.z += fmaxf(v1.z + ev1.z, 0.f);
            acc2.w += fmaxf(v1.w + ev1.w, 0.f);
        }
        if (j < cnt) {
            int pj0 = __shfl_sync(0xFFFFFFFFu, p, j);
            float4 v0 = *(const float4*)&g_h[(size_t)(pj0 & 0x1FFFF) * D + lane * 4];
            XFORM(v0);
            int t0 = pj0 >> 17;
            float4 ev0 = (t0 == 0) ? e0 : (t0 == 1) ? e1 : e2;
            acc.x += fmaxf(v0.x + ev0.x, 0.f);
            acc.y += fmaxf(v0.y + ev0.y, 0.f);
            acc.z += fmaxf(v0.z + ev0.z, 0.f);
            acc.w += fmaxf(v0.w + ev0.w, 0.f);
        }
    }
#undef XFORM
    float ep = 1.f + epsv[l];
    float4 xm = *(const float4*)&g_h[(size_t)node * D + lane * 4];
    if (NORM) {
        xm.x = fmaxf(xm.x * s1[0] + s2[0], 0.f);
        xm.y = fmaxf(xm.y * s1[1] + s2[1], 0.f);
        xm.z = fmaxf(xm.z * s1[2] + s2[2], 0.f);
        xm.w = fmaxf(xm.w * s1[3] + s2[3], 0.f);
    }
    float4 o;
    o.x = ep * xm.x + acc.x + acc2.x;
    o.y = ep * xm.y + acc.y + acc2.y;
    o.z = ep * xm.z + acc.z + acc2.z;
    o.w = ep * xm.w + acc.w + acc2.w;
    *(float4*)&g_x[(size_t)node * D + lane * 4] = o;
}

// ---------------- tensor-core GEMM (mma.sync tf32, 3xTF32 compensated) ----------------
// C[M,128] = act(A[M,128] @ W[128,128] + bias).  64-row tile, 2 CTAs/SM.
// Options: doZero (block 0 zeroes stats), doStats (fused BN stats), aNorm (BN at A-staging).
#define SSA 132
#define SSW 136
#define GEMM_SMEM ((64 * SSA + 128 * SSW) * 4)

__device__ __forceinline__ void tf32_split(float v, uint32_t& hi, uint32_t& lo) {
    uint32_t h;
    asm("cvt.rna.tf32.f32 %0, %1;" : "=r"(h) : "f"(v));
    float r = v - __uint_as_float(h);
    uint32_t l;
    asm("cvt.rna.tf32.f32 %0, %1;" : "=r"(l) : "f"(r));
    hi = h; lo = l;
}

__device__ __forceinline__ void mma8(float* c, const uint32_t* a, const uint32_t* b) {
    asm volatile("mma.sync.aligned.m16n8k8.row.col.f32.tf32.tf32.f32 "
                 "{%0,%1,%2,%3}, {%4,%5,%6,%7}, {%8,%9}, {%0,%1,%2,%3};"
                 : "+f"(c[0]), "+f"(c[1]), "+f"(c[2]), "+f"(c[3])
                 : "r"(a[0]), "r"(a[1]), "r"(a[2]), "r"(a[3]), "r"(b[0]), "r"(b[1]));
}

__global__ void __launch_bounds__(256, 2) k_gemm_tc(int aSel, int cSel,
                                                    const float* __restrict__ W,
                                                    const float* __restrict__ bias,
                                                    int M, int doRelu, int doStats, int doZero,
                                                    int aNorm,
                                                    const float* __restrict__ gamma,
                                                    const float* __restrict__ beta) {
    extern __shared__ float sm[];
    float* As = sm;                 // [64][SSA]
    float* Ws = sm + 64 * SSA;      // [128][SSW], layout [k][n]
    __shared__ float s1sh[128];
    __shared__ float s2sh[128];

    const float* A = bufsel(aSel);
    float* C = bufsel(cSel);

    int tid = threadIdx.x;
    int wid = tid >> 5;
    int lane = tid & 31;
    int row0 = blockIdx.x * 64;

    if (doZero && blockIdx.x == 0 && tid < 128) {
        g_sum[tid] = 0.f;
        g_ss[tid] = 0.f;
    }

    if (aNorm) {
        if (tid < 128) {
            float invM = 1.f / (float)M;
            float mu = g_sum[tid] * invM;
            float var = g_ss[tid] * invM - mu * mu;
            float a = gamma[tid] * rsqrtf(var + 1e-5f);
            s1sh[tid] = a;
            s2sh[tid] = beta[tid] - mu * a;
        }
        __syncthreads();
    }

    // stage A: 64 x 128 floats (zero-pad past M; optional norm transform)
    for (int i = tid; i < 2048; i += 256) {
        int r = i >> 5, q = i & 31;
        int gr = row0 + r;
        float4 v = make_float4(0.f, 0.f, 0.f, 0.f);
        if (gr < M) {
            v = *(const float4*)&A[(size_t)gr * D + q * 4];
            if (aNorm) {
                int f = q * 4;
                v.x = fmaxf(v.x * s1sh[f] + s2sh[f], 0.f);
                v.y = fmaxf(v.y * s1sh[f + 1] + s2sh[f + 1], 0.f);
                v.z = fmaxf(v.z * s1sh[f + 2] + s2sh[f + 2], 0.f);
                v.w = fmaxf(v.w * s1sh[f + 3] + s2sh[f + 3], 0.f);
            }
        }
        *(float4*)&As[r * SSA + q * 4] = v;
    }
    // stage W: direct copy, [k][n]
    for (int i = tid; i < 4096; i += 256) {
        int kr = i >> 5, q = i & 31;
        float4 v = *(const float4*)&W[kr * D + q * 4];
        *(float4*)&Ws[kr * SSW + q * 4] = v;
    }
    __syncthreads();

    const int wr = (wid & 1) * 32;   // row group base
    const int wc = (wid >> 1) * 32;  // col group base
    const int lr = lane >> 2;        // 0..7
    const int lc = lane & 3;         // 0..3

    float acc[2][4][4];
#pragma unroll
    for (int m = 0; m < 2; m++)
#pragma unroll
        for (int n = 0; n < 4; n++)
#pragma unroll
            for (int q = 0; q < 4; q++) acc[m][n][q] = 0.f;

#pragma unroll
    for (int k0 = 0; k0 < 128; k0 += 8) {
        uint32_t ah[2][4], al[2][4];
#pragma unroll
        for (int m = 0; m < 2; m++) {
            int r = wr + m * 16 + lr;
            float v0 = As[r * SSA + k0 + lc];
            float v1 = As[(r + 8) * SSA + k0 + lc];
            float v2 = As[r * SSA + k0 + lc + 4];
            float v3 = As[(r + 8) * SSA + k0 + lc + 4];
            tf32_split(v0, ah[m][0], al[m][0]);
            tf32_split(v1, ah[m][1], al[m][1]);
            tf32_split(v2, ah[m][2], al[m][2]);
            tf32_split(v3, ah[m][3], al[m][3]);
        }
        uint32_t bh[4][2], bl[4][2];
#pragma unroll
        for (int n = 0; n < 4; n++) {
            int col = wc + n * 8 + lr;
            float v0 = Ws[(k0 + lc) * SSW + col];
            float v1 = Ws[(k0 + lc + 4) * SSW + col];
            tf32_split(v0, bh[n][0], bl[n][0]);
            tf32_split(v1, bh[n][1], bl[n][1]);
        }
#pragma unroll
        for (int m = 0; m < 2; m++)
#pragma unroll
            for (int n = 0; n < 4; n++) {
                mma8(acc[m][n], ah[m], bh[n]);
                mma8(acc[m][n], ah[m], bl[n]);
                mma8(acc[m][n], al[m], bh[n]);
            }
    }

    // epilogue: bias + optional relu, float2 stores; optional fused BN stats
    float ps[4][2], pss[4][2];
#pragma unroll
    for (int n = 0; n < 4; n++)
#pragma unroll
        for (int q = 0; q < 2; q++) { ps[n][q] = 0.f; pss[n][q] = 0.f; }

#pragma unroll
    for (int m = 0; m < 2; m++) {
        int row = row0 + wr + m * 16 + lr;
#pragma unroll
        for (int n = 0; n < 4; n++) {
            int col = wc + n * 8 + lc * 2;
            float bx = bias[col], by = bias[col + 1];
            if (row < M) {
                float ox = acc[m][n][0] + bx;
                float oy = acc[m][n][1] + by;
                if (doStats) {
                    ps[n][0] += ox; pss[n][0] += ox * ox;
                    ps[n][1] += oy; pss[n][1] += oy * oy;
                }
                float2 o;
                o.x = doRelu ? fmaxf(ox, 0.f) : ox;
                o.y = doRelu ? fmaxf(oy, 0.f) : oy;
                *(float2*)&C[(size_t)row * D + col] = o;
            }
            if (row + 8 < M) {
                float ox = acc[m][n][2] + bx;
                float oy = acc[m][n][3] + by;
                if (doStats) {
                    ps[n][0] += ox; pss[n][0] += ox * ox;
                    ps[n][1] += oy; pss[n][1] += oy * oy;
                }
                float2 o;
                o.x = doRelu ? fmaxf(ox, 0.f) : ox;
                o.y = doRelu ? fmaxf(oy, 0.f) : oy;
                *(float2*)&C[(size_t)(row + 8) * D + col] = o;
            }
        }
    }

    if (doStats) {
        // reduce across lanes sharing the same columns (same lc, lr = 0..7)
#pragma unroll
        for (int n = 0; n < 4; n++)
#pragma unroll
            for (int q = 0; q < 2; q++) {
#pragma unroll
                for (int off = 4; off < 32; off <<= 1) {
                    ps[n][q]  += __shfl_xor_sync(0xFFFFFFFFu, ps[n][q], off);
                    pss[n][q] += __shfl_xor_sync(0xFFFFFFFFu, pss[n][q], off);
                }
            }
        if (lr == 0) {
#pragma unroll
            for (int n = 0; n < 4; n++) {
                int col = wc + n * 8 + lc * 2;
                atomicAdd(&g_sum[col], ps[n][0]);
                atomicAdd(&g_sum[col + 1], ps[n][1]);
                atomicAdd(&g_ss[col], pss[n][0]);
                atomicAdd(&g_ss[col + 1], pss[n][1]);
            }
        }
    }
}

// ---------------- head final dot ----------------
__global__ void k_head3(const float* __restrict__ w3, const float* __restrict__ b3,
                        float* __restrict__ out, int M) {
    int gwarp = (blockIdx.x * blockDim.x + threadIdx.x) >> 5;
    int lane = threadIdx.x & 31;
    if (gwarp >= M) return;
    float4 a = *(const float4*)&g_h2[(size_t)gwarp * D + lane * 4];
    float4 w = *(const float4*)&w3[lane * 4];
    float s = a.x * w.x + a.y * w.y + a.z * w.z + a.w * w.w;
#pragma unroll
    for (int o = 16; o > 0; o >>= 1)
        s += __shfl_down_sync(0xFFFFFFFFu, s, o);
    if (lane == 0) out[gwarp] = s + b3[0];
}

// ---------------- launcher ----------------
extern "C" void kernel_launch(void* const* d_in, const int* in_sizes, int n_in,
                              void* d_out, int out_size) {
    const int*   node_type  = (const int*)  d_in[0];
    const int*   edge_type  = (const int*)  d_in[1];
    const int*   edge_index = (const int*)  d_in[2];
    const float* node_emb   = (const float*)d_in[3];
    const float* edge_emb   = (const float*)d_in[4];
    const float* eps        = (const float*)d_in[5];
    const float* W1         = (const float*)d_in[6];
    const float* b1         = (const float*)d_in[7];
    const float* W2         = (const float*)d_in[8];
    const float* b2         = (const float*)d_in[9];
    const float* gamma      = (const float*)d_in[10];
    const float* beta       = (const float*)d_in[11];
    const float* hW1        = (const float*)d_in[12];
    const float* hb1        = (const float*)d_in[13];
    const float* hW2        = (const float*)d_in[14];
    const float* hb2        = (const float*)d_in[15];
    const float* hW3        = (const float*)d_in[16];
    const float* hb3        = (const float*)d_in[17];
    float* out = (float*)d_out;

    int N = in_sizes[0];
    int E = in_sizes[1];
    int gTiles = (N + 63) / 64;

    static int smemSet = 0;
    if (!smemSet) {
        cudaFuncSetAttribute(k_gemm_tc, cudaFuncAttributeMaxDynamicSharedMemorySize, GEMM_SMEM);
        smemSet = 1;
    }

    // CSR build
    k_zero_deg<<<(N + 255) / 256, 256>>>(N);
    k_hist<<<(E + 255) / 256, 256>>>(edge_index, E);
    k_scan1<<<1, 1024>>>(N, E);
    k_fill<<<(E + 255) / 256, 256>>>(edge_index, edge_type, E);

    // feature encoder -> g_h
    k_embed<<<(N * D + 255) / 256, 256>>>(node_type, node_emb, N);

    // GINE layers: agg (BN-apply fused for l>0), gemm1 (relu, zero stats), gemm2 (+stats)
    for (int l = 0; l < L; l++) {
        if (l == 0)
            k_agg<0><<<(N + 7) / 8, 256>>>(edge_emb, eps, l, N, gamma, beta);
        else
            k_agg<1><<<(N + 7) / 8, 256>>>(edge_emb, eps, l, N,
                                           gamma + (l - 1) * D, beta + (l - 1) * D);
        // g_x -> g_h2 (relu); block 0 zeroes stats for this layer
        k_gemm_tc<<<gTiles, 256, GEMM_SMEM>>>(0, 2, W1 + l * D * D, b1 + l * D,
                                              N, 1, 0, 1, 0, nullptr, nullptr);
        // g_h2 -> g_h (+stats)
        k_gemm_tc<<<gTiles, 256, GEMM_SMEM>>>(2, 1, W2 + l * D * D, b2 + l * D,
                                              N, 0, 1, 0, 0, nullptr, nullptr);
    }

    // head MLP: gemm1 applies final BN at A-staging (g_h -> g_x), then g_x -> g_h2
    k_gemm_tc<<<gTiles, 256, GEMM_SMEM>>>(1, 0, hW1, hb1, N, 1, 0, 0, 1,
                                          gamma + 2 * D, beta + 2 * D);
    k_gemm_tc<<<gTiles, 256, GEMM_SMEM>>>(0, 2, hW2, hb2, N, 1, 0, 0, 0, nullptr, nullptr);
    k_head3<<<(N + 7) / 8, 256>>>(hW3, hb3, out, N);
}

// round 9
// speedup vs baseline: 2.0264x; 1.2396x over previous
#include <cuda_runtime.h>
#include <cstdint>

#define NN 50000
#define EE 800000
#define D  128
#define L  3

// ---------------- scratch (device globals; no allocation APIs) ----------------
__device__ float g_x [NN * D];
__device__ float g_h [NN * D];
__device__ float g_h2[NN * D];
__device__ int   g_deg[NN];
__device__ int   g_off[NN + 1];
__device__ int   g_cur[NN];
__device__ int   g_csr[EE];                 // packed: src | (edge_type << 17)
__device__ float g_sum[D];
__device__ float g_ss [D];
__device__ uint32_t g_wh[8 * 128 * 64];     // W split hi: [w][n][kpair] bf16x2
__device__ uint32_t g_wl[8 * 128 * 64];     // W split lo

__device__ __forceinline__ float* bufsel(int s) {
    return s == 0 ? g_x : (s == 1 ? g_h : g_h2);
}

// pack two floats into bf16x2 (v0 low half / v1 high half) + residual pair
__device__ __forceinline__ void bf16_split2(float v0, float v1, uint32_t& hi, uint32_t& lo) {
    uint32_t h;
    asm("cvt.rn.bf16x2.f32 %0, %1, %2;" : "=r"(h) : "f"(v1), "f"(v0));
    float h0 = __uint_as_float(h << 16);
    float h1 = __uint_as_float(h & 0xFFFF0000u);
    float r0 = v0 - h0;
    float r1 = v1 - h1;
    uint32_t l;
    asm("cvt.rn.bf16x2.f32 %0, %1, %2;" : "=r"(l) : "f"(r1), "f"(r0));
    hi = h; lo = l;
}

__device__ __forceinline__ void mma16(float* c, const uint32_t* a, const uint32_t* b) {
    asm volatile("mma.sync.aligned.m16n8k16.row.col.f32.bf16.bf16.f32 "
                 "{%0,%1,%2,%3}, {%4,%5,%6,%7}, {%8,%9}, {%0,%1,%2,%3};"
                 : "+f"(c[0]), "+f"(c[1]), "+f"(c[2]), "+f"(c[3])
                 : "r"(a[0]), "r"(a[1]), "r"(a[2]), "r"(a[3]), "r"(b[0]), "r"(b[1]));
}

// ---------------- CSR build ----------------
__global__ void k_zero_deg(int n) {
    int i = blockIdx.x * blockDim.x + threadIdx.x;
    if (i < n) g_deg[i] = 0;
}
__global__ void k_hist(const int* __restrict__ ei, int E) {
    int e = blockIdx.x * blockDim.x + threadIdx.x;
    if (e < E) atomicAdd(&g_deg[ei[E + e]], 1);
}

// single-block exclusive scan over g_deg -> g_off, g_cur (warp-shuffle based)
__global__ void __launch_bounds__(1024) k_scan1(int n, int E) {
    __shared__ int wsum[32];
    __shared__ int wpre[32];
    __shared__ int stot;
    int t = threadIdx.x;
    int lane = t & 31;
    int w = t >> 5;
    int run = 0;
    for (int base = 0; base < n; base += 1024) {
        int i = base + t;
        int v = (i < n) ? g_deg[i] : 0;
        int s = v;
#pragma unroll
        for (int o = 1; o < 32; o <<= 1) {
            int x = __shfl_up_sync(0xFFFFFFFFu, s, o);
            if (lane >= o) s += x;
        }
        if (lane == 31) wsum[w] = s;
        __syncthreads();
        if (w == 0) {
            int x = wsum[lane];
            int ss = x;
#pragma unroll
            for (int o = 1; o < 32; o <<= 1) {
                int y = __shfl_up_sync(0xFFFFFFFFu, ss, o);
                if (lane >= o) ss += y;
            }
            wpre[lane] = ss - x;
            if (lane == 31) stot = ss;
        }
        __syncthreads();
        int excl = run + wpre[w] + s - v;
        if (i < n) { g_off[i] = excl; g_cur[i] = excl; }
        run += stot;
        __syncthreads();
    }
    if (t == 0) g_off[n] = E;
}

__global__ void k_fill(const int* __restrict__ ei, const int* __restrict__ et, int E) {
    int e = blockIdx.x * blockDim.x + threadIdx.x;
    if (e >= E) return;
    int dst = ei[E + e];
    int p = atomicAdd(&g_cur[dst], 1);
    g_csr[p] = ei[e] | (et[e] << 17);
}

// ---------------- feature encoder (writes g_h) ----------------
__global__ void k_embed(const int* __restrict__ nt, const float* __restrict__ nemb, int n) {
    int i = blockIdx.x * blockDim.x + threadIdx.x;
    if (i >= n * D) return;
    g_h[i] = nemb[nt[i >> 7] * D + (i & 127)];
}

// ---------------- weight pre-split: 8 matrices -> bf16 hi/lo pairs, [w][n][kpair] ----------------
__global__ void k_wsplit(const float* __restrict__ W1, const float* __restrict__ W2,
                         const float* __restrict__ hW1, const float* __restrict__ hW2) {
    int idx = blockIdx.x * blockDim.x + threadIdx.x;
    if (idx >= 8 * 128 * 64) return;
    int w = idx >> 13;
    int n = (idx >> 6) & 127;
    int i = idx & 63;
    const float* W;
    if (w < 6) W = ((w & 1) ? W2 : W1) + (w >> 1) * D * D;
    else W = (w == 6) ? hW1 : hW2;
    float v0 = W[(2 * i) * D + n];
    float v1 = W[(2 * i + 1) * D + n];
    uint32_t h, l;
    bf16_split2(v0, v1, h, l);
    g_wh[idx] = h;
    g_wl[idx] = l;
}

// ---------------- GINE aggregate (+ optional fused BN-apply of previous layer) ----------------
// reads g_h (NORM: x = relu(h*s1+s2), else x = h), writes g_x = (1+eps)x + sum relu(x_src + e)
// 4-way unrolled edge gather (MLP=4).
template <int NORM>
__global__ void __launch_bounds__(256) k_agg(const float* __restrict__ eemb,
                                             const float* __restrict__ epsv, int l, int n,
                                             const float* __restrict__ gamma,
                                             const float* __restrict__ beta) {
    int warp = (blockIdx.x * 256 + threadIdx.x) >> 5;
    int lane = threadIdx.x & 31;
    if (warp >= n) return;
    int node = warp;

    float s1[4], s2[4];
    if (NORM) {
        float invM = 1.f / (float)n;
#pragma unroll
        for (int c = 0; c < 4; c++) {
            int f = lane * 4 + c;
            float mu = g_sum[f] * invM;
            float var = g_ss[f] * invM - mu * mu;
            float a = gamma[f] * rsqrtf(var + 1e-5f);
            s1[c] = a;
            s2[c] = beta[f] - mu * a;
        }
    }

    float4 e0 = *(const float4*)&eemb[lane * 4];
    float4 e1 = *(const float4*)&eemb[D + lane * 4];
    float4 e2 = *(const float4*)&eemb[2 * D + lane * 4];
    int s = g_off[node], e = g_off[node + 1];
    float4 a0 = make_float4(0.f, 0.f, 0.f, 0.f);
    float4 a1 = make_float4(0.f, 0.f, 0.f, 0.f);
    float4 a2 = make_float4(0.f, 0.f, 0.f, 0.f);
    float4 a3 = make_float4(0.f, 0.f, 0.f, 0.f);

#define XFORM(v) do { if (NORM) { \
        v.x = fmaxf(v.x * s1[0] + s2[0], 0.f); \
        v.y = fmaxf(v.y * s1[1] + s2[1], 0.f); \
        v.z = fmaxf(v.z * s1[2] + s2[2], 0.f); \
        v.w = fmaxf(v.w * s1[3] + s2[3], 0.f); } } while (0)
#define ACC(A, V, T) do { \
        float4 ev = ((T) == 0) ? e0 : ((T) == 1) ? e1 : e2; \
        A.x += fmaxf(V.x + ev.x, 0.f); \
        A.y += fmaxf(V.y + ev.y, 0.f); \
        A.z += fmaxf(V.z + ev.z, 0.f); \
        A.w += fmaxf(V.w + ev.w, 0.f); } while (0)

    for (int base = s; base < e; base += 32) {
        int cnt = min(32, e - base);
        int p = (lane < cnt) ? g_csr[base + lane] : 0;
        int j = 0;
        for (; j + 3 < cnt; j += 4) {
            int p0 = __shfl_sync(0xFFFFFFFFu, p, j);
            int p1 = __shfl_sync(0xFFFFFFFFu, p, j + 1);
            int p2 = __shfl_sync(0xFFFFFFFFu, p, j + 2);
            int p3 = __shfl_sync(0xFFFFFFFFu, p, j + 3);
            float4 v0 = *(const float4*)&g_h[(size_t)(p0 & 0x1FFFF) * D + lane * 4];
            float4 v1 = *(const float4*)&g_h[(size_t)(p1 & 0x1FFFF) * D + lane * 4];
            float4 v2 = *(const float4*)&g_h[(size_t)(p2 & 0x1FFFF) * D + lane * 4];
            float4 v3 = *(const float4*)&g_h[(size_t)(p3 & 0x1FFFF) * D + lane * 4];
            XFORM(v0); XFORM(v1); XFORM(v2); XFORM(v3);
            ACC(a0, v0, p0 >> 17);
            ACC(a1, v1, p1 >> 17);
            ACC(a2, v2, p2 >> 17);
            ACC(a3, v3, p3 >> 17);
        }
        for (; j < cnt; j++) {
            int p0 = __shfl_sync(0xFFFFFFFFu, p, j);
            float4 v0 = *(const float4*)&g_h[(size_t)(p0 & 0x1FFFF) * D + lane * 4];
            XFORM(v0);
            ACC(a0, v0, p0 >> 17);
        }
    }
#undef ACC
#undef XFORM
    float ep = 1.f + epsv[l];
    float4 xm = *(const float4*)&g_h[(size_t)node * D + lane * 4];
    if (NORM) {
        xm.x = fmaxf(xm.x * s1[0] + s2[0], 0.f);
        xm.y = fmaxf(xm.y * s1[1] + s2[1], 0.f);
        xm.z = fmaxf(xm.z * s1[2] + s2[2], 0.f);
        xm.w = fmaxf(xm.w * s1[3] + s2[3], 0.f);
    }
    float4 o;
    o.x = ep * xm.x + (a0.x + a1.x) + (a2.x + a3.x);
    o.y = ep * xm.y + (a0.y + a1.y) + (a2.y + a3.y);
    o.z = ep * xm.z + (a0.z + a1.z) + (a2.z + a3.z);
    o.w = ep * xm.w + (a0.w + a1.w) + (a2.w + a3.w);
    *(float4*)&g_x[(size_t)node * D + lane * 4] = o;
}

// ---------------- tensor-core GEMM (mma.sync bf16 m16n8k16, 3-term split) ----------------
// C[M,128] = act(A[M,128] @ W[128,128] + bias).  64-row tile, 2 CTAs/SM.
// W pre-split (g_wh/g_wl). Options: doZero / doStats / aNorm (BN at A-staging).
#define SSA 132
#define SWPAD 68
#define GEMM_SMEM ((64 * SSA + 2 * 128 * SWPAD) * 4)

__global__ void __launch_bounds__(256, 2) k_gemm_tc(int aSel, int cSel, int wIdx,
                                                    const float* __restrict__ bias,
                                                    int M, int doRelu, int doStats, int doZero,
                                                    int aNorm,
                                                    const float* __restrict__ gamma,
                                                    const float* __restrict__ beta) {
    extern __shared__ float sm[];
    float* As = sm;                                  // [64][SSA]
    uint32_t* Whs = (uint32_t*)(sm + 64 * SSA);      // [128][SWPAD]
    uint32_t* Wls = Whs + 128 * SWPAD;               // [128][SWPAD]
    __shared__ float s1sh[128];
    __shared__ float s2sh[128];

    const float* A = bufsel(aSel);
    float* C = bufsel(cSel);

    int tid = threadIdx.x;
    int wid = tid >> 5;
    int lane = tid & 31;
    int row0 = blockIdx.x * 64;

    if (doZero && blockIdx.x == 0 && tid < 128) {
        g_sum[tid] = 0.f;
        g_ss[tid] = 0.f;
    }

    if (aNorm) {
        if (tid < 128) {
            float invM = 1.f / (float)M;
            float mu = g_sum[tid] * invM;
            float var = g_ss[tid] * invM - mu * mu;
            float a = gamma[tid] * rsqrtf(var + 1e-5f);
            s1sh[tid] = a;
            s2sh[tid] = beta[tid] - mu * a;
        }
        __syncthreads();
    }

    // stage A: 64 x 128 floats (zero-pad past M; optional norm transform)
    for (int i = tid; i < 2048; i += 256) {
        int r = i >> 5, q = i & 31;
        int gr = row0 + r;
        float4 v = make_float4(0.f, 0.f, 0.f, 0.f);
        if (gr < M) {
            v = *(const float4*)&A[(size_t)gr * D + q * 4];
            if (aNorm) {
                int f = q * 4;
                v.x = fmaxf(v.x * s1sh[f] + s2sh[f], 0.f);
                v.y = fmaxf(v.y * s1sh[f + 1] + s2sh[f + 1], 0.f);
                v.z = fmaxf(v.z * s1sh[f + 2] + s2sh[f + 2], 0.f);
                v.w = fmaxf(v.w * s1sh[f + 3] + s2sh[f + 3], 0.f);
            }
        }
        *(float4*)&As[r * SSA + q * 4] = v;
    }
    // stage pre-split W: [n=128][64 kpairs] -> padded [128][SWPAD]
    {
        const uint32_t* wh = g_wh + wIdx * 8192;
        const uint32_t* wl = g_wl + wIdx * 8192;
        for (int j = tid; j < 8192; j += 256) {
            int nrow = j >> 6, i = j & 63;
            Whs[nrow * SWPAD + i] = wh[j];
            Wls[nrow * SWPAD + i] = wl[j];
        }
    }
    __syncthreads();

    const int wr = (wid & 1) * 32;   // row group base
    const int wc = (wid >> 1) * 32;  // col group base
    const int lr = lane >> 2;        // 0..7
    const int lc = lane & 3;         // 0..3

    float acc[2][4][4];
#pragma unroll
    for (int m = 0; m < 2; m++)
#pragma unroll
        for (int n = 0; n < 4; n++)
#pragma unroll
            for (int q = 0; q < 4; q++) acc[m][n][q] = 0.f;

#pragma unroll
    for (int s = 0; s < 8; s++) {        // k0 = 16*s
        int kb = 16 * s + 2 * lc;
        uint32_t ah[2][4], al[2][4];
#pragma unroll
        for (int m = 0; m < 2; m++) {
            int r0 = (wr + m * 16 + lr) * SSA;
            int r1 = r0 + 8 * SSA;
            bf16_split2(As[r0 + kb],     As[r0 + kb + 1], ah[m][0], al[m][0]);
            bf16_split2(As[r1 + kb],     As[r1 + kb + 1], ah[m][1], al[m][1]);
            bf16_split2(As[r0 + kb + 8], As[r0 + kb + 9], ah[m][2], al[m][2]);
            bf16_split2(As[r1 + kb + 8], As[r1 + kb + 9], ah[m][3], al[m][3]);
        }
        uint32_t bh[4][2], bl[4][2];
#pragma unroll
        for (int n = 0; n < 4; n++) {
            int col = (wc + n * 8 + lr) * SWPAD + 8 * s + lc;
            bh[n][0] = Whs[col];
            bh[n][1] = Whs[col + 4];
            bl[n][0] = Wls[col];
            bl[n][1] = Wls[col + 4];
        }
#pragma unroll
        for (int m = 0; m < 2; m++)
#pragma unroll
            for (int n = 0; n < 4; n++) {
                mma16(acc[m][n], ah[m], bh[n]);
                mma16(acc[m][n], ah[m], bl[n]);
                mma16(acc[m][n], al[m], bh[n]);
            }
    }

    // epilogue: bias + optional relu; optional fused BN stats
    float ps[4][2], pss[4][2];
#pragma unroll
    for (int n = 0; n < 4; n++)
#pragma unroll
        for (int q = 0; q < 2; q++) { ps[n][q] = 0.f; pss[n][q] = 0.f; }

#pragma unroll
    for (int m = 0; m < 2; m++) {
        int row = row0 + wr + m * 16 + lr;
#pragma unroll
        for (int n = 0; n < 4; n++) {
            int col = wc + n * 8 + lc * 2;
            float bx = bias[col], by = bias[col + 1];
            if (row < M) {
                float ox = acc[m][n][0] + bx;
                float oy = acc[m][n][1] + by;
                if (doStats) {
                    ps[n][0] += ox; pss[n][0] += ox * ox;
                    ps[n][1] += oy; pss[n][1] += oy * oy;
                }
                float2 o;
                o.x = doRelu ? fmaxf(ox, 0.f) : ox;
                o.y = doRelu ? fmaxf(oy, 0.f) : oy;
                *(float2*)&C[(size_t)row * D + col] = o;
            }
            if (row + 8 < M) {
                float ox = acc[m][n][2] + bx;
                float oy = acc[m][n][3] + by;
                if (doStats) {
                    ps[n][0] += ox; pss[n][0] += ox * ox;
                    ps[n][1] += oy; pss[n][1] += oy * oy;
                }
                float2 o;
                o.x = doRelu ? fmaxf(ox, 0.f) : ox;
                o.y = doRelu ? fmaxf(oy, 0.f) : oy;
                *(float2*)&C[(size_t)(row + 8) * D + col] = o;
            }
        }
    }

    if (doStats) {
#pragma unroll
        for (int n = 0; n < 4; n++)
#pragma unroll
            for (int q = 0; q < 2; q++) {
#pragma unroll
                for (int off = 4; off < 32; off <<= 1) {
                    ps[n][q]  += __shfl_xor_sync(0xFFFFFFFFu, ps[n][q], off);
                    pss[n][q] += __shfl_xor_sync(0xFFFFFFFFu, pss[n][q], off);
                }
            }
        if (lr == 0) {
#pragma unroll
            for (int n = 0; n < 4; n++) {
                int col = wc + n * 8 + lc * 2;
                atomicAdd(&g_sum[col], ps[n][0]);
                atomicAdd(&g_sum[col + 1], ps[n][1]);
                atomicAdd(&g_ss[col], pss[n][0]);
                atomicAdd(&g_ss[col + 1], pss[n][1]);
            }
        }
    }
}

// ---------------- head final dot ----------------
__global__ void k_head3(const float* __restrict__ w3, const float* __restrict__ b3,
                        float* __restrict__ out, int M) {
    int gwarp = (blockIdx.x * blockDim.x + threadIdx.x) >> 5;
    int lane = threadIdx.x & 31;
    if (gwarp >= M) return;
    float4 a = *(const float4*)&g_h2[(size_t)gwarp * D + lane * 4];
    float4 w = *(const float4*)&w3[lane * 4];
    float s = a.x * w.x + a.y * w.y + a.z * w.z + a.w * w.w;
#pragma unroll
    for (int o = 16; o > 0; o >>= 1)
        s += __shfl_down_sync(0xFFFFFFFFu, s, o);
    if (lane == 0) out[gwarp] = s + b3[0];
}

// ---------------- launcher ----------------
extern "C" void kernel_launch(void* const* d_in, const int* in_sizes, int n_in,
                              void* d_out, int out_size) {
    const int*   node_type  = (const int*)  d_in[0];
    const int*   edge_type  = (const int*)  d_in[1];
    const int*   edge_index = (const int*)  d_in[2];
    const float* node_emb   = (const float*)d_in[3];
    const float* edge_emb   = (const float*)d_in[4];
    const float* eps        = (const float*)d_in[5];
    const float* W1         = (const float*)d_in[6];
    const float* b1         = (const float*)d_in[7];
    const float* W2         = (const float*)d_in[8];
    const float* b2         = (const float*)d_in[9];
    const float* gamma      = (const float*)d_in[10];
    const float* beta       = (const float*)d_in[11];
    const float* hW1        = (const float*)d_in[12];
    const float* hb1        = (const float*)d_in[13];
    const float* hW2        = (const float*)d_in[14];
    const float* hb2        = (const float*)d_in[15];
    const float* hW3        = (const float*)d_in[16];
    const float* hb3        = (const float*)d_in[17];
    float* out = (float*)d_out;

    int N = in_sizes[0];
    int E = in_sizes[1];
    int gTiles = (N + 63) / 64;

    static int smemSet = 0;
    if (!smemSet) {
        cudaFuncSetAttribute(k_gemm_tc, cudaFuncAttributeMaxDynamicSharedMemorySize, GEMM_SMEM);
        smemSet = 1;
    }

    // CSR build
    k_zero_deg<<<(N + 255) / 256, 256>>>(N);
    k_hist<<<(E + 255) / 256, 256>>>(edge_index, E);
    k_scan1<<<1, 1024>>>(N, E);
    k_fill<<<(E + 255) / 256, 256>>>(edge_index, edge_type, E);

    // feature encoder -> g_h ; weight pre-split
    k_embed<<<(N * D + 255) / 256, 256>>>(node_type, node_emb, N);
    k_wsplit<<<(8 * 128 * 64 + 255) / 256, 256>>>(W1, W2, hW1, hW2);

    // GINE layers: agg (BN-apply fused for l>0), gemm1 (relu, zero stats), gemm2 (+stats)
    for (int l = 0; l < L; l++) {
        if (l == 0)
            k_agg<0><<<(N + 7) / 8, 256>>>(edge_emb, eps, l, N, gamma, beta);
        else
            k_agg<1><<<(N + 7) / 8, 256>>>(edge_emb, eps, l, N,
                                           gamma + (l - 1) * D, beta + (l - 1) * D);
        // g_x -> g_h2 (relu); block 0 zeroes stats for this layer
        k_gemm_tc<<<gTiles, 256, GEMM_SMEM>>>(0, 2, 2 * l, b1 + l * D,
                                              N, 1, 0, 1, 0, nullptr, nullptr);
        // g_h2 -> g_h (+stats)
        k_gemm_tc<<<gTiles, 256, GEMM_SMEM>>>(2, 1, 2 * l + 1, b2 + l * D,
                                              N, 0, 1, 0, 0, nullptr, nullptr);
    }

    // head MLP: gemm1 applies final BN at A-staging (g_h -> g_x), then g_x -> g_h2
    k_gemm_tc<<<gTiles, 256, GEMM_SMEM>>>(1, 0, 6, hb1, N, 1, 0, 0, 1,
                                          gamma + 2 * D, beta + 2 * D);
    k_gemm_tc<<<gTiles, 256, GEMM_SMEM>>>(0, 2, 7, hb2, N, 1, 0, 0, 0, nullptr, nullptr);
    k_head3<<<(N + 7) / 8, 256>>>(hW3, hb3, out, N);
}

// round 10
// speedup vs baseline: 2.2738x; 1.1221x over previous
#include <cuda_runtime.h>
#include <cstdint>

#define NN 50000
#define EE 800000
#define D  128
#define L  3

// ---------------- scratch (device globals; no allocation APIs) ----------------
__device__ float g_x [NN * D];
__device__ float g_h [NN * D];
__device__ float g_h2[NN * D];
__device__ int   g_deg[NN];
__device__ int   g_off[NN + 1];
__device__ int   g_cur[NN];
__device__ int   g_csr[EE];                 // packed: src | et<<17 | nt(src)<<19
__device__ float g_sum[3 * D];              // per-layer BN stats
__device__ float g_ss [3 * D];
__device__ uint32_t g_wh[8 * 128 * 64];     // W split hi: [w][n][kpair] bf16x2
__device__ uint32_t g_wl[8 * 128 * 64];     // W split lo

__device__ __forceinline__ float* bufsel(int s) {
    return s == 0 ? g_x : (s == 1 ? g_h : g_h2);
}

// pack two floats into bf16x2 (v0 low half / v1 high half) + residual pair
__device__ __forceinline__ void bf16_split2(float v0, float v1, uint32_t& hi, uint32_t& lo) {
    uint32_t h;
    asm("cvt.rn.bf16x2.f32 %0, %1, %2;" : "=r"(h) : "f"(v1), "f"(v0));
    float h0 = __uint_as_float(h << 16);
    float h1 = __uint_as_float(h & 0xFFFF0000u);
    float r0 = v0 - h0;
    float r1 = v1 - h1;
    uint32_t l;
    asm("cvt.rn.bf16x2.f32 %0, %1, %2;" : "=r"(l) : "f"(r1), "f"(r0));
    hi = h; lo = l;
}

__device__ __forceinline__ void mma16(float* c, const uint32_t* a, const uint32_t* b) {
    asm volatile("mma.sync.aligned.m16n8k16.row.col.f32.bf16.bf16.f32 "
                 "{%0,%1,%2,%3}, {%4,%5,%6,%7}, {%8,%9}, {%0,%1,%2,%3};"
                 : "+f"(c[0]), "+f"(c[1]), "+f"(c[2]), "+f"(c[3])
                 : "r"(a[0]), "r"(a[1]), "r"(a[2]), "r"(a[3]), "r"(b[0]), "r"(b[1]));
}

// ---------------- CSR build ----------------
__global__ void k_zero_deg(int n) {
    int i = blockIdx.x * blockDim.x + threadIdx.x;
    if (i < n) g_deg[i] = 0;
}
__global__ void k_hist(const int* __restrict__ ei, int E) {
    int e = blockIdx.x * blockDim.x + threadIdx.x;
    if (e < E) atomicAdd(&g_deg[ei[E + e]], 1);
}

// single-block exclusive scan over g_deg -> g_off, g_cur (warp-shuffle based)
__global__ void __launch_bounds__(1024) k_scan1(int n, int E) {
    __shared__ int wsum[32];
    __shared__ int wpre[32];
    __shared__ int stot;
    int t = threadIdx.x;
    int lane = t & 31;
    int w = t >> 5;
    int run = 0;
    for (int base = 0; base < n; base += 1024) {
        int i = base + t;
        int v = (i < n) ? g_deg[i] : 0;
        int s = v;
#pragma unroll
        for (int o = 1; o < 32; o <<= 1) {
            int x = __shfl_up_sync(0xFFFFFFFFu, s, o);
            if (lane >= o) s += x;
        }
        if (lane == 31) wsum[w] = s;
        __syncthreads();
        if (w == 0) {
            int x = wsum[lane];
            int ss = x;
#pragma unroll
            for (int o = 1; o < 32; o <<= 1) {
                int y = __shfl_up_sync(0xFFFFFFFFu, ss, o);
                if (lane >= o) ss += y;
            }
            wpre[lane] = ss - x;
            if (lane == 31) stot = ss;
        }
        __syncthreads();
        int excl = run + wpre[w] + s - v;
        if (i < n) { g_off[i] = excl; g_cur[i] = excl; }
        run += stot;
        __syncthreads();
    }
    if (t == 0) g_off[n] = E;
}

// fill also packs node_type[src] (2 bits) so layer-0 agg needs no feature loads
__global__ void k_fill(const int* __restrict__ ei, const int* __restrict__ et,
                       const int* __restrict__ nt, int E) {
    int e = blockIdx.x * blockDim.x + threadIdx.x;
    if (e >= E) return;
    int src = ei[e];
    int dst = ei[E + e];
    int p = atomicAdd(&g_cur[dst], 1);
    g_csr[p] = src | (et[e] << 17) | (nt[src] << 19);
}

// ---------------- weight pre-split + stats zero ----------------
__global__ void k_wsplit(const float* __restrict__ W1, const float* __restrict__ W2,
                         const float* __restrict__ hW1, const float* __restrict__ hW2) {
    int idx = blockIdx.x * blockDim.x + threadIdx.x;
    if (idx < 3 * D) { g_sum[idx] = 0.f; g_ss[idx] = 0.f; }
    if (idx >= 8 * 128 * 64) return;
    int w = idx >> 13;
    int n = (idx >> 6) & 127;
    int i = idx & 63;
    const float* W;
    if (w < 6) W = ((w & 1) ? W2 : W1) + (w >> 1) * D * D;
    else W = (w == 6) ? hW1 : hW2;
    float v0 = W[(2 * i) * D + n];
    float v1 = W[(2 * i + 1) * D + n];
    uint32_t h, l;
    bf16_split2(v0, v1, h, l);
    g_wh[idx] = h;
    g_wl[idx] = l;
}

// ---------------- GINE aggregate ----------------
// MODE 0 (layer 0): source features = node_emb[node_type] held in registers; no gather.
// MODE 1: reads g_h with fused BN-apply (x = relu(h*s1+s2)) from stats[statsIdx].
// Writes g_x = (1+eps)*x_node + sum relu(x_src + e).
template <int MODE>
__global__ void __launch_bounds__(256) k_agg(const float* __restrict__ eemb,
                                             const float* __restrict__ epsv, int l, int n,
                                             const float* __restrict__ gamma,
                                             const float* __restrict__ beta, int statsIdx,
                                             const int* __restrict__ nt,
                                             const float* __restrict__ nemb) {
    int warp = (blockIdx.x * 256 + threadIdx.x) >> 5;
    int lane = threadIdx.x & 31;
    if (warp >= n) return;
    int node = warp;

    float s1[4], s2[4];
    float4 nr0, nr1, nr2, nr3;
    if (MODE == 0) {
        nr0 = *(const float4*)&nemb[lane * 4];
        nr1 = *(const float4*)&nemb[D + lane * 4];
        nr2 = *(const float4*)&nemb[2 * D + lane * 4];
        nr3 = *(const float4*)&nemb[3 * D + lane * 4];
    } else {
        float invM = 1.f / (float)n;
        int sb = statsIdx * D;
#pragma unroll
        for (int c = 0; c < 4; c++) {
            int f = lane * 4 + c;
            float mu = g_sum[sb + f] * invM;
            float var = g_ss[sb + f] * invM - mu * mu;
            float a = gamma[f] * rsqrtf(var + 1e-5f);
            s1[c] = a;
            s2[c] = beta[f] - mu * a;
        }
    }

    float4 e0 = *(const float4*)&eemb[lane * 4];
    float4 e1 = *(const float4*)&eemb[D + lane * 4];
    float4 e2 = *(const float4*)&eemb[2 * D + lane * 4];
    int s = g_off[node], e = g_off[node + 1];
    float4 a0 = make_float4(0.f, 0.f, 0.f, 0.f);
    float4 a1 = make_float4(0.f, 0.f, 0.f, 0.f);
    float4 a2 = make_float4(0.f, 0.f, 0.f, 0.f);
    float4 a3 = make_float4(0.f, 0.f, 0.f, 0.f);

#define NSEL(T) ((T) == 0 ? nr0 : (T) == 1 ? nr1 : (T) == 2 ? nr2 : nr3)
#define GETV(V, P) do { \
        if (MODE == 0) { int tn = ((P) >> 19) & 3; V = NSEL(tn); } \
        else { \
            V = *(const float4*)&g_h[(size_t)((P) & 0x1FFFF) * D + lane * 4]; \
            V.x = fmaxf(V.x * s1[0] + s2[0], 0.f); \
            V.y = fmaxf(V.y * s1[1] + s2[1], 0.f); \
            V.z = fmaxf(V.z * s1[2] + s2[2], 0.f); \
            V.w = fmaxf(V.w * s1[3] + s2[3], 0.f); } } while (0)
#define ACC(A, V, P) do { \
        int te = ((P) >> 17) & 3; \
        float4 ev = (te == 0) ? e0 : (te == 1) ? e1 : e2; \
        A.x += fmaxf(V.x + ev.x, 0.f); \
        A.y += fmaxf(V.y + ev.y, 0.f); \
        A.z += fmaxf(V.z + ev.z, 0.f); \
        A.w += fmaxf(V.w + ev.w, 0.f); } while (0)

    for (int base = s; base < e; base += 32) {
        int cnt = min(32, e - base);
        int p = (lane < cnt) ? g_csr[base + lane] : 0;
        int j = 0;
        for (; j + 3 < cnt; j += 4) {
            int p0 = __shfl_sync(0xFFFFFFFFu, p, j);
            int p1 = __shfl_sync(0xFFFFFFFFu, p, j + 1);
            int p2 = __shfl_sync(0xFFFFFFFFu, p, j + 2);
            int p3 = __shfl_sync(0xFFFFFFFFu, p, j + 3);
            float4 v0, v1, v2, v3;
            GETV(v0, p0); GETV(v1, p1); GETV(v2, p2); GETV(v3, p3);
            ACC(a0, v0, p0);
            ACC(a1, v1, p1);
            ACC(a2, v2, p2);
            ACC(a3, v3, p3);
        }
        for (; j < cnt; j++) {
            int p0 = __shfl_sync(0xFFFFFFFFu, p, j);
            float4 v0;
            GETV(v0, p0);
            ACC(a0, v0, p0);
        }
    }

    float ep = 1.f + epsv[l];
    float4 xm;
    if (MODE == 0) {
        int tn = nt[node];
        xm = NSEL(tn);
    } else {
        xm = *(const float4*)&g_h[(size_t)node * D + lane * 4];
        xm.x = fmaxf(xm.x * s1[0] + s2[0], 0.f);
        xm.y = fmaxf(xm.y * s1[1] + s2[1], 0.f);
        xm.z = fmaxf(xm.z * s1[2] + s2[2], 0.f);
        xm.w = fmaxf(xm.w * s1[3] + s2[3], 0.f);
    }
#undef ACC
#undef GETV
#undef NSEL
    float4 o;
    o.x = ep * xm.x + (a0.x + a1.x) + (a2.x + a3.x);
    o.y = ep * xm.y + (a0.y + a1.y) + (a2.y + a3.y);
    o.z = ep * xm.z + (a0.z + a1.z) + (a2.z + a3.z);
    o.w = ep * xm.w + (a0.w + a1.w) + (a2.w + a3.w);
    *(float4*)&g_x[(size_t)node * D + lane * 4] = o;
}

// ---------------- fused 2-GEMM MLP (mma.sync bf16 m16n8k16, 3-term split) ----------------
// C = act2(relu(A@WA + bA) @ WB + bB).  64-row tile, 2 CTAs/SM.
// C1 kept in SMEM (reuses A buffer); WB restaged over WA between mainloops.
#define SSA 132
#define SWPAD 68
#define GEMM_SMEM ((64 * SSA + 2 * 128 * SWPAD) * 4)

__device__ __forceinline__ void mlp_mainloop(const float* As, const uint32_t* Whs,
                                             const uint32_t* Wls, float acc[2][4][4],
                                             int wr, int wc, int lr, int lc) {
#pragma unroll
    for (int s = 0; s < 8; s++) {
        int kb = 16 * s + 2 * lc;
        uint32_t ah[2][4], al[2][4];
#pragma unroll
        for (int m = 0; m < 2; m++) {
            int r0 = (wr + m * 16 + lr) * SSA;
            int r1 = r0 + 8 * SSA;
            bf16_split2(As[r0 + kb],     As[r0 + kb + 1], ah[m][0], al[m][0]);
            bf16_split2(As[r1 + kb],     As[r1 + kb + 1], ah[m][1], al[m][1]);
            bf16_split2(As[r0 + kb + 8], As[r0 + kb + 9], ah[m][2], al[m][2]);
            bf16_split2(As[r1 + kb + 8], As[r1 + kb + 9], ah[m][3], al[m][3]);
        }
        uint32_t bh[4][2], bl[4][2];
#pragma unroll
        for (int n = 0; n < 4; n++) {
            int col = (wc + n * 8 + lr) * SWPAD + 8 * s + lc;
            bh[n][0] = Whs[col];
            bh[n][1] = Whs[col + 4];
            bl[n][0] = Wls[col];
            bl[n][1] = Wls[col + 4];
        }
#pragma unroll
        for (int m = 0; m < 2; m++)
#pragma unroll
            for (int n = 0; n < 4; n++) {
                mma16(acc[m][n], ah[m], bh[n]);
                mma16(acc[m][n], ah[m], bl[n]);
                mma16(acc[m][n], al[m], bh[n]);
            }
    }
}

__global__ void __launch_bounds__(256, 2) k_mlp(int aSel, int cSel, int wIdxA, int wIdxB,
                                                const float* __restrict__ bA,
                                                const float* __restrict__ bB,
                                                int M, int reluB, int statsIdx,
                                                int aNorm,
                                                const float* __restrict__ gamma,
                                                const float* __restrict__ beta, int normIdx) {
    extern __shared__ float sm[];
    float* As = sm;                                  // [64][SSA]
    uint32_t* Whs = (uint32_t*)(sm + 64 * SSA);      // [128][SWPAD]
    uint32_t* Wls = Whs + 128 * SWPAD;               // [128][SWPAD]
    __shared__ float s1sh[128];
    __shared__ float s2sh[128];

    const float* A = bufsel(aSel);
    float* C = bufsel(cSel);

    int tid = threadIdx.x;
    int wid = tid >> 5;
    int lane = tid & 31;
    int row0 = blockIdx.x * 64;

    if (aNorm) {
        if (tid < 128) {
            float invM = 1.f / (float)M;
            int sb = normIdx * D;
            float mu = g_sum[sb + tid] * invM;
            float var = g_ss[sb + tid] * invM - mu * mu;
            float a = gamma[tid] * rsqrtf(var + 1e-5f);
            s1sh[tid] = a;
            s2sh[tid] = beta[tid] - mu * a;
        }
        __syncthreads();
    }

    // stage A (zero-pad past M; optional BN transform)
    for (int i = tid; i < 2048; i += 256) {
        int r = i >> 5, q = i & 31;
        int gr = row0 + r;
        float4 v = make_float4(0.f, 0.f, 0.f, 0.f);
        if (gr < M) {
            v = *(const float4*)&A[(size_t)gr * D + q * 4];
            if (aNorm) {
                int f = q * 4;
                v.x = fmaxf(v.x * s1sh[f] + s2sh[f], 0.f);
                v.y = fmaxf(v.y * s1sh[f + 1] + s2sh[f + 1], 0.f);
                v.z = fmaxf(v.z * s1sh[f + 2] + s2sh[f + 2], 0.f);
                v.w = fmaxf(v.w * s1sh[f + 3] + s2sh[f + 3], 0.f);
            }
        }
        *(float4*)&As[r * SSA + q * 4] = v;
    }
    // stage WA
    {
        const uint32_t* wh = g_wh + wIdxA * 8192;
        const uint32_t* wl = g_wl + wIdxA * 8192;
        for (int j = tid; j < 8192; j += 256) {
            int nrow = j >> 6, i = j & 63;
            Whs[nrow * SWPAD + i] = wh[j];
            Wls[nrow * SWPAD + i] = wl[j];
        }
    }
    __syncthreads();

    const int wr = (wid & 1) * 32;
    const int wc = (wid >> 1) * 32;
    const int lr = lane >> 2;
    const int lc = lane & 3;

    float acc[2][4][4];
#pragma unroll
    for (int m = 0; m < 2; m++)
#pragma unroll
        for (int n = 0; n < 4; n++)
#pragma unroll
            for (int q = 0; q < 4; q++) acc[m][n][q] = 0.f;

    mlp_mainloop(As, Whs, Wls, acc, wr, wc, lr, lc);
    __syncthreads();   // everyone done reading As / WA

    // C1 = relu(acc + bA) -> As ; restage WB
#pragma unroll
    for (int m = 0; m < 2; m++) {
        int rl = wr + m * 16 + lr;
#pragma unroll
        for (int n = 0; n < 4; n++) {
            int col = wc + n * 8 + lc * 2;
            float bx = bA[col], by = bA[col + 1];
            float2 o0, o1;
            o0.x = fmaxf(acc[m][n][0] + bx, 0.f);
            o0.y = fmaxf(acc[m][n][1] + by, 0.f);
            o1.x = fmaxf(acc[m][n][2] + bx, 0.f);
            o1.y = fmaxf(acc[m][n][3] + by, 0.f);
            *(float2*)&As[rl * SSA + col] = o0;
            *(float2*)&As[(rl + 8) * SSA + col] = o1;
        }
    }
    {
        const uint32_t* wh = g_wh + wIdxB * 8192;
        const uint32_t* wl = g_wl + wIdxB * 8192;
        for (int j = tid; j < 8192; j += 256) {
            int nrow = j >> 6, i = j & 63;
            Whs[nrow * SWPAD + i] = wh[j];
            Wls[nrow * SWPAD + i] = wl[j];
        }
    }
    __syncthreads();

#pragma unroll
    for (int m = 0; m < 2; m++)
#pragma unroll
        for (int n = 0; n < 4; n++)
#pragma unroll
            for (int q = 0; q < 4; q++) acc[m][n][q] = 0.f;

    mlp_mainloop(As, Whs, Wls, acc, wr, wc, lr, lc);

    // epilogue: bias bB + optional relu; optional fused BN stats
    float ps[4][2], pss[4][2];
#pragma unroll
    for (int n = 0; n < 4; n++)
#pragma unroll
        for (int q = 0; q < 2; q++) { ps[n][q] = 0.f; pss[n][q] = 0.f; }

#pragma unroll
    for (int m = 0; m < 2; m++) {
        int row = row0 + wr + m * 16 + lr;
#pragma unroll
        for (int n = 0; n < 4; n++) {
            int col = wc + n * 8 + lc * 2;
            float bx = bB[col], by = bB[col + 1];
            if (row < M) {
                float ox = acc[m][n][0] + bx;
                float oy = acc[m][n][1] + by;
                if (statsIdx >= 0) {
                    ps[n][0] += ox; pss[n][0] += ox * ox;
                    ps[n][1] += oy; pss[n][1] += oy * oy;
                }
                float2 o;
                o.x = reluB ? fmaxf(ox, 0.f) : ox;
                o.y = reluB ? fmaxf(oy, 0.f) : oy;
                *(float2*)&C[(size_t)row * D + col] = o;
            }
            if (row + 8 < M) {
                float ox = acc[m][n][2] + bx;
                float oy = acc[m][n][3] + by;
                if (statsIdx >= 0) {
                    ps[n][0] += ox; pss[n][0] += ox * ox;
                    ps[n][1] += oy; pss[n][1] += oy * oy;
                }
                float2 o;
                o.x = reluB ? fmaxf(ox, 0.f) : ox;
                o.y = reluB ? fmaxf(oy, 0.f) : oy;
                *(float2*)&C[(size_t)(row + 8) * D + col] = o;
            }
        }
    }

    if (statsIdx >= 0) {
        int sb = statsIdx * D;
#pragma unroll
        for (int n = 0; n < 4; n++)
#pragma unroll
            for (int q = 0; q < 2; q++) {
#pragma unroll
                for (int off = 4; off < 32; off <<= 1) {
                    ps[n][q]  += __shfl_xor_sync(0xFFFFFFFFu, ps[n][q], off);
                    pss[n][q] += __shfl_xor_sync(0xFFFFFFFFu, pss[n][q], off);
                }
            }
        if (lr == 0) {
#pragma unroll
            for (int n = 0; n < 4; n++) {
                int col = wc + n * 8 + lc * 2;
                atomicAdd(&g_sum[sb + col], ps[n][0]);
                atomicAdd(&g_sum[sb + col + 1], ps[n][1]);
                atomicAdd(&g_ss[sb + col], pss[n][0]);
                atomicAdd(&g_ss[sb + col + 1], pss[n][1]);
            }
        }
    }
}

// ---------------- head final dot ----------------
__global__ void k_head3(const float* __restrict__ w3, const float* __restrict__ b3,
                        float* __restrict__ out, int M) {
    int gwarp = (blockIdx.x * blockDim.x + threadIdx.x) >> 5;
    int lane = threadIdx.x & 31;
    if (gwarp >= M) return;
    float4 a = *(const float4*)&g_h2[(size_t)gwarp * D + lane * 4];
    float4 w = *(const float4*)&w3[lane * 4];
    float s = a.x * w.x + a.y * w.y + a.z * w.z + a.w * w.w;
#pragma unroll
    for (int o = 16; o > 0; o >>= 1)
        s += __shfl_down_sync(0xFFFFFFFFu, s, o);
    if (lane == 0) out[gwarp] = s + b3[0];
}

// ---------------- launcher ----------------
extern "C" void kernel_launch(void* const* d_in, const int* in_sizes, int n_in,
                              void* d_out, int out_size) {
    const int*   node_type  = (const int*)  d_in[0];
    const int*   edge_type  = (const int*)  d_in[1];
    const int*   edge_index = (const int*)  d_in[2];
    const float* node_emb   = (const float*)d_in[3];
    const float* edge_emb   = (const float*)d_in[4];
    const float* eps        = (const float*)d_in[5];
    const float* W1         = (const float*)d_in[6];
    const float* b1         = (const float*)d_in[7];
    const float* W2         = (const float*)d_in[8];
    const float* b2         = (const float*)d_in[9];
    const float* gamma      = (const float*)d_in[10];
    const float* beta       = (const float*)d_in[11];
    const float* hW1        = (const float*)d_in[12];
    const float* hb1        = (const float*)d_in[13];
    const float* hW2        = (const float*)d_in[14];
    const float* hb2        = (const float*)d_in[15];
    const float* hW3        = (const float*)d_in[16];
    const float* hb3        = (const float*)d_in[17];
    float* out = (float*)d_out;

    int N = in_sizes[0];
    int E = in_sizes[1];
    int gTiles = (N + 63) / 64;

    static int smemSet = 0;
    if (!smemSet) {
        cudaFuncSetAttribute(k_mlp, cudaFuncAttributeMaxDynamicSharedMemorySize, GEMM_SMEM);
        smemSet = 1;
    }

    // CSR build (fill packs node_type of src)
    k_zero_deg<<<(N + 255) / 256, 256>>>(N);
    k_hist<<<(E + 255) / 256, 256>>>(edge_index, E);
    k_scan1<<<1, 1024>>>(N, E);
    k_fill<<<(E + 255) / 256, 256>>>(edge_index, edge_type, node_type, E);

    // weight pre-split (+ zero all per-layer stats)
    k_wsplit<<<(8 * 128 * 64 + 255) / 256, 256>>>(W1, W2, hW1, hW2);

    // GINE layers: agg (embed fused at l=0, BN fused at l>0) then fused 2-GEMM MLP (+stats)
    for (int l = 0; l < L; l++) {
        if (l == 0)
            k_agg<0><<<(N + 7) / 8, 256>>>(edge_emb, eps, 0, N, nullptr, nullptr, -1,
                                           node_type, node_emb);
        else
            k_agg<1><<<(N + 7) / 8, 256>>>(edge_emb, eps, l, N,
                                           gamma + (l - 1) * D, beta + (l - 1) * D, l - 1,
                                           nullptr, nullptr);
        k_mlp<<<gTiles, 256, GEMM_SMEM>>>(0, 1, 2 * l, 2 * l + 1, b1 + l * D, b2 + l * D,
                                          N, 0, l, 0, nullptr, nullptr, 0);
    }

    // head: BN(stats 2) at A-staging, both layers relu, out -> g_h2; then final dot
    k_mlp<<<gTiles, 256, GEMM_SMEM>>>(1, 2, 6, 7, hb1, hb2, N, 1, -1,
                                      1, gamma + 2 * D, beta + 2 * D, 2);
    k_head3<<<(N + 7) / 8, 256>>>(hW3, hb3, out, N);
}

// round 11
// speedup vs baseline: 2.3236x; 1.0219x over previous
#include <cuda_runtime.h>
#include <cstdint>

#define NN 50000
#define EE 800000
#define D  128
#define L  3

// ---------------- scratch (device globals; no allocation APIs) ----------------
__device__ float g_x [NN * D];
__device__ float g_h [NN * D];
__device__ int   g_deg[NN];
__device__ int   g_off[NN + 1];
__device__ int   g_cur[NN];
__device__ int   g_csr[EE];                 // packed: src | et<<17 | nt(src)<<19
__device__ float g_sum[3 * D];              // per-layer BN stats
__device__ float g_ss [3 * D];
__device__ uint32_t g_wh[8 * 128 * 64];     // W split hi: [w][n][kpair] bf16x2
__device__ uint32_t g_wl[8 * 128 * 64];     // W split lo

__device__ __forceinline__ float* bufsel(int s) {
    return s == 0 ? g_x : g_h;
}

// pack two floats into bf16x2 (v0 low half / v1 high half) + residual pair
__device__ __forceinline__ void bf16_split2(float v0, float v1, uint32_t& hi, uint32_t& lo) {
    uint32_t h;
    asm("cvt.rn.bf16x2.f32 %0, %1, %2;" : "=r"(h) : "f"(v1), "f"(v0));
    float h0 = __uint_as_float(h << 16);
    float h1 = __uint_as_float(h & 0xFFFF0000u);
    float r0 = v0 - h0;
    float r1 = v1 - h1;
    uint32_t l;
    asm("cvt.rn.bf16x2.f32 %0, %1, %2;" : "=r"(l) : "f"(r1), "f"(r0));
    hi = h; lo = l;
}

__device__ __forceinline__ void mma16(float* c, const uint32_t* a, const uint32_t* b) {
    asm volatile("mma.sync.aligned.m16n8k16.row.col.f32.bf16.bf16.f32 "
                 "{%0,%1,%2,%3}, {%4,%5,%6,%7}, {%8,%9}, {%0,%1,%2,%3};"
                 : "+f"(c[0]), "+f"(c[1]), "+f"(c[2]), "+f"(c[3])
                 : "r"(a[0]), "r"(a[1]), "r"(a[2]), "r"(a[3]), "r"(b[0]), "r"(b[1]));
}

// ---------------- CSR build ----------------
__global__ void k_zero_deg(int n) {
    int i = blockIdx.x * blockDim.x + threadIdx.x;
    if (i < n) g_deg[i] = 0;
}
__global__ void k_hist(const int* __restrict__ ei, int E) {
    int e = blockIdx.x * blockDim.x + threadIdx.x;
    if (e < E) atomicAdd(&g_deg[ei[E + e]], 1);
}

// single-block exclusive scan over g_deg -> g_off, g_cur (warp-shuffle based)
__global__ void __launch_bounds__(1024) k_scan1(int n, int E) {
    __shared__ int wsum[32];
    __shared__ int wpre[32];
    __shared__ int stot;
    int t = threadIdx.x;
    int lane = t & 31;
    int w = t >> 5;
    int run = 0;
    for (int base = 0; base < n; base += 1024) {
        int i = base + t;
        int v = (i < n) ? g_deg[i] : 0;
        int s = v;
#pragma unroll
        for (int o = 1; o < 32; o <<= 1) {
            int x = __shfl_up_sync(0xFFFFFFFFu, s, o);
            if (lane >= o) s += x;
        }
        if (lane == 31) wsum[w] = s;
        __syncthreads();
        if (w == 0) {
            int x = wsum[lane];
            int ss = x;
#pragma unroll
            for (int o = 1; o < 32; o <<= 1) {
                int y = __shfl_up_sync(0xFFFFFFFFu, ss, o);
                if (lane >= o) ss += y;
            }
            wpre[lane] = ss - x;
            if (lane == 31) stot = ss;
        }
        __syncthreads();
        int excl = run + wpre[w] + s - v;
        if (i < n) { g_off[i] = excl; g_cur[i] = excl; }
        run += stot;
        __syncthreads();
    }
    if (t == 0) g_off[n] = E;
}

// fill also packs node_type[src] (2 bits) so layer-0 agg needs no feature loads
__global__ void k_fill(const int* __restrict__ ei, const int* __restrict__ et,
                       const int* __restrict__ nt, int E) {
    int e = blockIdx.x * blockDim.x + threadIdx.x;
    if (e >= E) return;
    int src = ei[e];
    int dst = ei[E + e];
    int p = atomicAdd(&g_cur[dst], 1);
    g_csr[p] = src | (et[e] << 17) | (nt[src] << 19);
}

// ---------------- weight pre-split + stats zero ----------------
__global__ void k_wsplit(const float* __restrict__ W1, const float* __restrict__ W2,
                         const float* __restrict__ hW1, const float* __restrict__ hW2) {
    int idx = blockIdx.x * blockDim.x + threadIdx.x;
    if (idx < 3 * D) { g_sum[idx] = 0.f; g_ss[idx] = 0.f; }
    if (idx >= 8 * 128 * 64) return;
    int w = idx >> 13;
    int n = (idx >> 6) & 127;
    int i = idx & 63;
    const float* W;
    if (w < 6) W = ((w & 1) ? W2 : W1) + (w >> 1) * D * D;
    else W = (w == 6) ? hW1 : hW2;
    float v0 = W[(2 * i) * D + n];
    float v1 = W[(2 * i + 1) * D + n];
    uint32_t h, l;
    bf16_split2(v0, v1, h, l);
    g_wh[idx] = h;
    g_wl[idx] = l;
}

// ---------------- GINE aggregate ----------------
// MODE 0 (layer 0): source features = node_emb[node_type] held in registers; no gather.
// MODE 1: reads g_h with fused BN-apply (x = relu(h*s1+s2)) from stats[statsIdx].
// Writes g_x = (1+eps)*x_node + sum relu(x_src + e).
template <int MODE>
__global__ void __launch_bounds__(256) k_agg(const float* __restrict__ eemb,
                                             const float* __restrict__ epsv, int l, int n,
                                             const float* __restrict__ gamma,
                                             const float* __restrict__ beta, int statsIdx,
                                             const int* __restrict__ nt,
                                             const float* __restrict__ nemb) {
    int warp = (blockIdx.x * 256 + threadIdx.x) >> 5;
    int lane = threadIdx.x & 31;
    if (warp >= n) return;
    int node = warp;

    float s1[4], s2[4];
    float4 nr0, nr1, nr2, nr3;
    if (MODE == 0) {
        nr0 = *(const float4*)&nemb[lane * 4];
        nr1 = *(const float4*)&nemb[D + lane * 4];
        nr2 = *(const float4*)&nemb[2 * D + lane * 4];
        nr3 = *(const float4*)&nemb[3 * D + lane * 4];
    } else {
        float invM = 1.f / (float)n;
        int sb = statsIdx * D;
#pragma unroll
        for (int c = 0; c < 4; c++) {
            int f = lane * 4 + c;
            float mu = g_sum[sb + f] * invM;
            float var = g_ss[sb + f] * invM - mu * mu;
            float a = gamma[f] * rsqrtf(var + 1e-5f);
            s1[c] = a;
            s2[c] = beta[f] - mu * a;
        }
    }

    float4 e0 = *(const float4*)&eemb[lane * 4];
    float4 e1 = *(const float4*)&eemb[D + lane * 4];
    float4 e2 = *(const float4*)&eemb[2 * D + lane * 4];
    int s = g_off[node], e = g_off[node + 1];
    float4 a0 = make_float4(0.f, 0.f, 0.f, 0.f);
    float4 a1 = make_float4(0.f, 0.f, 0.f, 0.f);
    float4 a2 = make_float4(0.f, 0.f, 0.f, 0.f);
    float4 a3 = make_float4(0.f, 0.f, 0.f, 0.f);

#define NSEL(T) ((T) == 0 ? nr0 : (T) == 1 ? nr1 : (T) == 2 ? nr2 : nr3)
#define GETV(V, P) do { \
        if (MODE == 0) { int tn = ((P) >> 19) & 3; V = NSEL(tn); } \
        else { \
            V = *(const float4*)&g_h[(size_t)((P) & 0x1FFFF) * D + lane * 4]; \
            V.x = fmaxf(V.x * s1[0] + s2[0], 0.f); \
            V.y = fmaxf(V.y * s1[1] + s2[1], 0.f); \
            V.z = fmaxf(V.z * s1[2] + s2[2], 0.f); \
            V.w = fmaxf(V.w * s1[3] + s2[3], 0.f); } } while (0)
#define ACC(A, V, P) do { \
        int te = ((P) >> 17) & 3; \
        float4 ev = (te == 0) ? e0 : (te == 1) ? e1 : e2; \
        A.x += fmaxf(V.x + ev.x, 0.f); \
        A.y += fmaxf(V.y + ev.y, 0.f); \
        A.z += fmaxf(V.z + ev.z, 0.f); \
        A.w += fmaxf(V.w + ev.w, 0.f); } while (0)

    for (int base = s; base < e; base += 32) {
        int cnt = min(32, e - base);
        int p = (lane < cnt) ? g_csr[base + lane] : 0;
        int j = 0;
        for (; j + 3 < cnt; j += 4) {
            int p0 = __shfl_sync(0xFFFFFFFFu, p, j);
            int p1 = __shfl_sync(0xFFFFFFFFu, p, j + 1);
            int p2 = __shfl_sync(0xFFFFFFFFu, p, j + 2);
            int p3 = __shfl_sync(0xFFFFFFFFu, p, j + 3);
            float4 v0, v1, v2, v3;
            GETV(v0, p0); GETV(v1, p1); GETV(v2, p2); GETV(v3, p3);
            ACC(a0, v0, p0);
            ACC(a1, v1, p1);
            ACC(a2, v2, p2);
            ACC(a3, v3, p3);
        }
        for (; j < cnt; j++) {
            int p0 = __shfl_sync(0xFFFFFFFFu, p, j);
            float4 v0;
            GETV(v0, p0);
            ACC(a0, v0, p0);
        }
    }

    float ep = 1.f + epsv[l];
    float4 xm;
    if (MODE == 0) {
        int tn = nt[node];
        xm = NSEL(tn);
    } else {
        xm = *(const float4*)&g_h[(size_t)node * D + lane * 4];
        xm.x = fmaxf(xm.x * s1[0] + s2[0], 0.f);
        xm.y = fmaxf(xm.y * s1[1] + s2[1], 0.f);
        xm.z = fmaxf(xm.z * s1[2] + s2[2], 0.f);
        xm.w = fmaxf(xm.w * s1[3] + s2[3], 0.f);
    }
#undef ACC
#undef GETV
#undef NSEL
    float4 o;
    o.x = ep * xm.x + (a0.x + a1.x) + (a2.x + a3.x);
    o.y = ep * xm.y + (a0.y + a1.y) + (a2.y + a3.y);
    o.z = ep * xm.z + (a0.z + a1.z) + (a2.z + a3.z);
    o.w = ep * xm.w + (a0.w + a1.w) + (a2.w + a3.w);
    *(float4*)&g_x[(size_t)node * D + lane * 4] = o;
}

// ---------------- fused 2-GEMM MLP (mma.sync bf16 m16n8k16, 3-term split) ----------------
// C = act2(relu(A@WA + bA) @ WB + bB).  64-row tile, 2 CTAs/SM.
// A and C1 stored PRE-SPLIT in SMEM (Ahi/Alo) -> mainloop is pure LDS+mma.
// HEAD=1: second-GEMM output dot-reduced against w3 in-kernel; writes out[row] directly.
#define SWPAD 68
#define GEMM_SMEM ((64 + 64 + 128 + 128) * SWPAD * 4)   // Ahi, Alo, Whs, Wls

__device__ __forceinline__ void mlp_mainloop(const uint32_t* Ahi, const uint32_t* Alo,
                                             const uint32_t* Whs, const uint32_t* Wls,
                                             float acc[2][4][4],
                                             int wr, int wc, int lr, int lc) {
#pragma unroll
    for (int s = 0; s < 8; s++) {
        int kp = 8 * s + lc;
        uint32_t ah[2][4], al[2][4];
#pragma unroll
        for (int m = 0; m < 2; m++) {
            int r0 = (wr + m * 16 + lr) * SWPAD;
            int r1 = r0 + 8 * SWPAD;
            ah[m][0] = Ahi[r0 + kp];
            ah[m][1] = Ahi[r1 + kp];
            ah[m][2] = Ahi[r0 + kp + 4];
            ah[m][3] = Ahi[r1 + kp + 4];
            al[m][0] = Alo[r0 + kp];
            al[m][1] = Alo[r1 + kp];
            al[m][2] = Alo[r0 + kp + 4];
            al[m][3] = Alo[r1 + kp + 4];
        }
        uint32_t bh[4][2], bl[4][2];
#pragma unroll
        for (int n = 0; n < 4; n++) {
            int col = (wc + n * 8 + lr) * SWPAD + kp;
            bh[n][0] = Whs[col];
            bh[n][1] = Whs[col + 4];
            bl[n][0] = Wls[col];
            bl[n][1] = Wls[col + 4];
        }
#pragma unroll
        for (int m = 0; m < 2; m++)
#pragma unroll
            for (int n = 0; n < 4; n++) {
                mma16(acc[m][n], ah[m], bh[n]);
                mma16(acc[m][n], ah[m], bl[n]);
                mma16(acc[m][n], al[m], bh[n]);
            }
    }
}

template <int HEAD>
__global__ void __launch_bounds__(256, 2) k_mlp(int aSel, int cSel, int wIdxA, int wIdxB,
                                                const float* __restrict__ bA,
                                                const float* __restrict__ bB,
                                                int M, int reluB, int statsIdx,
                                                int aNorm,
                                                const float* __restrict__ gamma,
                                                const float* __restrict__ beta, int normIdx,
                                                const float* __restrict__ w3,
                                                const float* __restrict__ b3,
                                                float* __restrict__ out) {
    extern __shared__ uint32_t smu[];
    uint32_t* Ahi = smu;                       // [64][SWPAD]
    uint32_t* Alo = Ahi + 64 * SWPAD;          // [64][SWPAD]
    uint32_t* Whs = Alo + 64 * SWPAD;          // [128][SWPAD]
    uint32_t* Wls = Whs + 128 * SWPAD;         // [128][SWPAD]
    __shared__ float s1sh[128];
    __shared__ float s2sh[128];

    const float* A = bufsel(aSel);
    float* C = bufsel(cSel);

    int tid = threadIdx.x;
    int wid = tid >> 5;
    int lane = tid & 31;
    int row0 = blockIdx.x * 64;

    if (aNorm) {
        if (tid < 128) {
            float invM = 1.f / (float)M;
            int sb = normIdx * D;
            float mu = g_sum[sb + tid] * invM;
            float var = g_ss[sb + tid] * invM - mu * mu;
            float a = gamma[tid] * rsqrtf(var + 1e-5f);
            s1sh[tid] = a;
            s2sh[tid] = beta[tid] - mu * a;
        }
        __syncthreads();
    }

    // stage A pre-split (zero-pad past M; optional BN transform)
    for (int i = tid; i < 2048; i += 256) {
        int r = i >> 5, q = i & 31;          // q = float4 index (2 kpairs)
        int gr = row0 + r;
        float4 v = make_float4(0.f, 0.f, 0.f, 0.f);
        if (gr < M) {
            v = *(const float4*)&A[(size_t)gr * D + q * 4];
            if (aNorm) {
                int f = q * 4;
                v.x = fmaxf(v.x * s1sh[f] + s2sh[f], 0.f);
                v.y = fmaxf(v.y * s1sh[f + 1] + s2sh[f + 1], 0.f);
                v.z = fmaxf(v.z * s1sh[f + 2] + s2sh[f + 2], 0.f);
                v.w = fmaxf(v.w * s1sh[f + 3] + s2sh[f + 3], 0.f);
            }
        }
        uint32_t h0, l0, h1, l1;
        bf16_split2(v.x, v.y, h0, l0);
        bf16_split2(v.z, v.w, h1, l1);
        int base = r * SWPAD + 2 * q;
        Ahi[base] = h0; Ahi[base + 1] = h1;
        Alo[base] = l0; Alo[base + 1] = l1;
    }
    // stage WA
    {
        const uint32_t* wh = g_wh + wIdxA * 8192;
        const uint32_t* wl = g_wl + wIdxA * 8192;
        for (int j = tid; j < 8192; j += 256) {
            int nrow = j >> 6, i = j & 63;
            Whs[nrow * SWPAD + i] = wh[j];
            Wls[nrow * SWPAD + i] = wl[j];
        }
    }
    __syncthreads();

    const int wr = (wid & 1) * 32;
    const int wc = (wid >> 1) * 32;
    const int lr = lane >> 2;
    const int lc = lane & 3;

    float acc[2][4][4];
#pragma unroll
    for (int m = 0; m < 2; m++)
#pragma unroll
        for (int n = 0; n < 4; n++)
#pragma unroll
            for (int q = 0; q < 4; q++) acc[m][n][q] = 0.f;

    mlp_mainloop(Ahi, Alo, Whs, Wls, acc, wr, wc, lr, lc);
    __syncthreads();   // everyone done reading Ahi/Alo/WA

    // C1 = relu(acc + bA), written pre-split -> Ahi/Alo ; restage WB
#pragma unroll
    for (int m = 0; m < 2; m++) {
        int rl = wr + m * 16 + lr;
#pragma unroll
        for (int n = 0; n < 4; n++) {
            int col = wc + n * 8 + lc * 2;
            int cp = col >> 1;               // column pair = kpair of second GEMM
            float bx = bA[col], by = bA[col + 1];
            float x0 = fmaxf(acc[m][n][0] + bx, 0.f);
            float y0 = fmaxf(acc[m][n][1] + by, 0.f);
            float x1 = fmaxf(acc[m][n][2] + bx, 0.f);
            float y1 = fmaxf(acc[m][n][3] + by, 0.f);
            uint32_t h, l;
            bf16_split2(x0, y0, h, l);
            Ahi[rl * SWPAD + cp] = h;
            Alo[rl * SWPAD + cp] = l;
            bf16_split2(x1, y1, h, l);
            Ahi[(rl + 8) * SWPAD + cp] = h;
            Alo[(rl + 8) * SWPAD + cp] = l;
        }
    }
    {
        const uint32_t* wh = g_wh + wIdxB * 8192;
        const uint32_t* wl = g_wl + wIdxB * 8192;
        for (int j = tid; j < 8192; j += 256) {
            int nrow = j >> 6, i = j & 63;
            Whs[nrow * SWPAD + i] = wh[j];
            Wls[nrow * SWPAD + i] = wl[j];
        }
    }
    __syncthreads();

#pragma unroll
    for (int m = 0; m < 2; m++)
#pragma unroll
        for (int n = 0; n < 4; n++)
#pragma unroll
            for (int q = 0; q < 4; q++) acc[m][n][q] = 0.f;

    mlp_mainloop(Ahi, Alo, Whs, Wls, acc, wr, wc, lr, lc);

    if (HEAD) {
        // write C2 = relu(acc + bB) fp32 into SMEM (reuse W buffers), then dot with w3
        __syncthreads();                       // all warps done reading WB
        float* Cs = (float*)Whs;               // [64][132] floats (33 KB <= 68 KB)
#pragma unroll
        for (int m = 0; m < 2; m++) {
            int rl = wr + m * 16 + lr;
#pragma unroll
            for (int n = 0; n < 4; n++) {
                int col = wc + n * 8 + lc * 2;
                float bx = bB[col], by = bB[col + 1];
                float2 o0, o1;
                o0.x = fmaxf(acc[m][n][0] + bx, 0.f);
                o0.y = fmaxf(acc[m][n][1] + by, 0.f);
                o1.x = fmaxf(acc[m][n][2] + bx, 0.f);
                o1.y = fmaxf(acc[m][n][3] + by, 0.f);
                *(float2*)&Cs[rl * 132 + col] = o0;
                *(float2*)&Cs[(rl + 8) * 132 + col] = o1;
            }
        }
        __syncthreads();
        float4 w = *(const float4*)&w3[lane * 4];
        float bias3 = b3[0];
#pragma unroll
        for (int r8 = 0; r8 < 8; r8++) {
            int row = wid * 8 + r8;
            float4 a = *(const float4*)&Cs[row * 132 + lane * 4];
            float s = a.x * w.x + a.y * w.y + a.z * w.z + a.w * w.w;
#pragma unroll
            for (int o = 16; o > 0; o >>= 1)
                s += __shfl_down_sync(0xFFFFFFFFu, s, o);
            if (lane == 0 && row0 + row < M)
                out[row0 + row] = s + bias3;
        }
        return;
    }

    // epilogue: bias bB + optional relu; optional fused BN stats
    float ps[4][2], pss[4][2];
#pragma unroll
    for (int n = 0; n < 4; n++)
#pragma unroll
        for (int q = 0; q < 2; q++) { ps[n][q] = 0.f; pss[n][q] = 0.f; }

#pragma unroll
    for (int m = 0; m < 2; m++) {
        int row = row0 + wr + m * 16 + lr;
#pragma unroll
        for (int n = 0; n < 4; n++) {
            int col = wc + n * 8 + lc * 2;
            float bx = bB[col], by = bB[col + 1];
            if (row < M) {
                float ox = acc[m][n][0] + bx;
                float oy = acc[m][n][1] + by;
                if (statsIdx >= 0) {
                    ps[n][0] += ox; pss[n][0] += ox * ox;
                    ps[n][1] += oy; pss[n][1] += oy * oy;
                }
                float2 o;
                o.x = reluB ? fmaxf(ox, 0.f) : ox;
                o.y = reluB ? fmaxf(oy, 0.f) : oy;
                *(float2*)&C[(size_t)row * D + col] = o;
            }
            if (row + 8 < M) {
                float ox = acc[m][n][2] + bx;
                float oy = acc[m][n][3] + by;
                if (statsIdx >= 0) {
                    ps[n][0] += ox; pss[n][0] += ox * ox;
                    ps[n][1] += oy; pss[n][1] += oy * oy;
                }
                float2 o;
                o.x = reluB ? fmaxf(ox, 0.f) : ox;
                o.y = reluB ? fmaxf(oy, 0.f) : oy;
                *(float2*)&C[(size_t)(row + 8) * D + col] = o;
            }
        }
    }

    if (statsIdx >= 0) {
        int sb = statsIdx * D;
#pragma unroll
        for (int n = 0; n < 4; n++)
#pragma unroll
            for (int q = 0; q < 2; q++) {
#pragma unroll
                for (int off = 4; off < 32; off <<= 1) {
                    ps[n][q]  += __shfl_xor_sync(0xFFFFFFFFu, ps[n][q], off);
                    pss[n][q] += __shfl_xor_sync(0xFFFFFFFFu, pss[n][q], off);
                }
            }
        if (lr == 0) {
#pragma unroll
            for (int n = 0; n < 4; n++) {
                int col = wc + n * 8 + lc * 2;
                atomicAdd(&g_sum[sb + col], ps[n][0]);
                atomicAdd(&g_sum[sb + col + 1], ps[n][1]);
                atomicAdd(&g_ss[sb + col], pss[n][0]);
                atomicAdd(&g_ss[sb + col + 1], pss[n][1]);
            }
        }
    }
}

// ---------------- launcher ----------------
extern "C" void kernel_launch(void* const* d_in, const int* in_sizes, int n_in,
                              void* d_out, int out_size) {
    const int*   node_type  = (const int*)  d_in[0];
    const int*   edge_type  = (const int*)  d_in[1];
    const int*   edge_index = (const int*)  d_in[2];
    const float* node_emb   = (const float*)d_in[3];
    const float* edge_emb   = (const float*)d_in[4];
    const float* eps        = (const float*)d_in[5];
    const float* W1         = (const float*)d_in[6];
    const float* b1         = (const float*)d_in[7];
    const float* W2         = (const float*)d_in[8];
    const float* b2         = (const float*)d_in[9];
    const float* gamma      = (const float*)d_in[10];
    const float* beta       = (const float*)d_in[11];
    const float* hW1        = (const float*)d_in[12];
    const float* hb1        = (const float*)d_in[13];
    const float* hW2        = (const float*)d_in[14];
    const float* hb2        = (const float*)d_in[15];
    const float* hW3        = (const float*)d_in[16];
    const float* hb3        = (const float*)d_in[17];
    float* out = (float*)d_out;

    int N = in_sizes[0];
    int E = in_sizes[1];
    int gTiles = (N + 63) / 64;

    static int smemSet = 0;
    if (!smemSet) {
        cudaFuncSetAttribute(k_mlp<0>, cudaFuncAttributeMaxDynamicSharedMemorySize, GEMM_SMEM);
        cudaFuncSetAttribute(k_mlp<1>, cudaFuncAttributeMaxDynamicSharedMemorySize, GEMM_SMEM);
        smemSet = 1;
    }

    // CSR build (fill packs node_type of src)
    k_zero_deg<<<(N + 255) / 256, 256>>>(N);
    k_hist<<<(E + 255) / 256, 256>>>(edge_index, E);
    k_scan1<<<1, 1024>>>(N, E);
    k_fill<<<(E + 255) / 256, 256>>>(edge_index, edge_type, node_type, E);

    // weight pre-split (+ zero all per-layer stats)
    k_wsplit<<<(8 * 128 * 64 + 255) / 256, 256>>>(W1, W2, hW1, hW2);

    // GINE layers: agg (embed fused at l=0, BN fused at l>0) then fused 2-GEMM MLP (+stats)
    for (int l = 0; l < L; l++) {
        if (l == 0)
            k_agg<0><<<(N + 7) / 8, 256>>>(edge_emb, eps, 0, N, nullptr, nullptr, -1,
                                           node_type, node_emb);
        else
            k_agg<1><<<(N + 7) / 8, 256>>>(edge_emb, eps, l, N,
                                           gamma + (l - 1) * D, beta + (l - 1) * D, l - 1,
                                           nullptr, nullptr);
        k_mlp<0><<<gTiles, 256, GEMM_SMEM>>>(0, 1, 2 * l, 2 * l + 1, b1 + l * D, b2 + l * D,
                                             N, 0, l, 0, nullptr, nullptr, 0,
                                             nullptr, nullptr, nullptr);
    }

    // head: BN(stats 2) at A-staging, fused head MLP + final dot -> out
    k_mlp<1><<<gTiles, 256, GEMM_SMEM>>>(1, 0, 6, 7, hb1, hb2, N, 1, -1,
                                         1, gamma + 2 * D, beta + 2 * D, 2,
                                         hW3, hb3, out);
}

// round 12
// speedup vs baseline: 2.5222x; 1.0854x over previous
#include <cuda_runtime.h>
#include <cstdint>

#define NN 50000
#define EE 800000
#define D  128
#define L  3

// ---------------- scratch (device globals; no allocation APIs) ----------------
__device__ float g_x [NN * D];              // ping-pong activation buffers
__device__ float g_h [NN * D];
__device__ int   g_deg[NN];
__device__ int   g_off[NN + 1];
__device__ int   g_cur[NN];
__device__ int   g_part[256];
__device__ int   g_csr[EE];                 // packed: src | et<<17 | nt(src)<<19
__device__ float g_sum[3 * D];              // per-layer BN stats
__device__ float g_ss [3 * D];
__device__ uint32_t g_wh[8 * 128 * 64];     // W split hi: [w][n][kpair] bf16x2
__device__ uint32_t g_wl[8 * 128 * 64];     // W split lo

__device__ __forceinline__ float* bufsel(int s) {
    return s == 0 ? g_x : g_h;
}

// pack two floats into bf16x2 (v0 low half / v1 high half) + residual pair
__device__ __forceinline__ void bf16_split2(float v0, float v1, uint32_t& hi, uint32_t& lo) {
    uint32_t h;
    asm("cvt.rn.bf16x2.f32 %0, %1, %2;" : "=r"(h) : "f"(v1), "f"(v0));
    float h0 = __uint_as_float(h << 16);
    float h1 = __uint_as_float(h & 0xFFFF0000u);
    float r0 = v0 - h0;
    float r1 = v1 - h1;
    uint32_t l;
    asm("cvt.rn.bf16x2.f32 %0, %1, %2;" : "=r"(l) : "f"(r1), "f"(r0));
    hi = h; lo = l;
}

__device__ __forceinline__ void mma16(float* c, const uint32_t* a, const uint32_t* b) {
    asm volatile("mma.sync.aligned.m16n8k16.row.col.f32.bf16.bf16.f32 "
                 "{%0,%1,%2,%3}, {%4,%5,%6,%7}, {%8,%9}, {%0,%1,%2,%3};"
                 : "+f"(c[0]), "+f"(c[1]), "+f"(c[2]), "+f"(c[3])
                 : "r"(a[0]), "r"(a[1]), "r"(a[2]), "r"(a[3]), "r"(b[0]), "r"(b[1]));
}

// ---------------- CSR build ----------------
__global__ void k_zero_deg(int n) {
    int i = blockIdx.x * blockDim.x + threadIdx.x;
    if (i < n) g_deg[i] = 0;
}
__global__ void k_hist(const int* __restrict__ ei, int E) {
    int e = blockIdx.x * blockDim.x + threadIdx.x;
    if (e < E) atomicAdd(&g_deg[ei[E + e]], 1);
}
__global__ void k_scan_partial(int n) {
    __shared__ int sh[256];
    int t = threadIdx.x;
    int i = blockIdx.x * 256 + t;
    sh[t] = (i < n) ? g_deg[i] : 0;
    __syncthreads();
    for (int s = 128; s > 0; s >>= 1) { if (t < s) sh[t] += sh[t + s]; __syncthreads(); }
    if (t == 0) g_part[blockIdx.x] = sh[0];
}
__global__ void k_scan_part(int nb) {
    __shared__ int sh[256];
    int t = threadIdx.x;
    sh[t] = (t < nb) ? g_part[t] : 0;
    __syncthreads();
    for (int o = 1; o < 256; o <<= 1) {
        int v = (t >= o) ? sh[t - o] : 0;
        __syncthreads(); sh[t] += v; __syncthreads();
    }
    if (t < nb) g_part[t] = (t == 0) ? 0 : sh[t - 1];
}
__global__ void k_scan_write(int n, int E) {
    __shared__ int sh[256];
    int t = threadIdx.x;
    int i = blockIdx.x * 256 + t;
    int orig = (i < n) ? g_deg[i] : 0;
    sh[t] = orig;
    __syncthreads();
    for (int o = 1; o < 256; o <<= 1) {
        int v = (t >= o) ? sh[t - o] : 0;
        __syncthreads(); sh[t] += v; __syncthreads();
    }
    if (i < n) {
        int excl = g_part[blockIdx.x] + sh[t] - orig;
        g_off[i] = excl;
        g_cur[i] = excl;
    }
    if (blockIdx.x == 0 && t == 0) g_off[n] = E;
}

// fill also packs node_type[src] (2 bits) so layer-0 gather needs no feature loads
__global__ void k_fill(const int* __restrict__ ei, const int* __restrict__ et,
                       const int* __restrict__ nt, int E) {
    int e = blockIdx.x * blockDim.x + threadIdx.x;
    if (e >= E) return;
    int src = ei[e];
    int dst = ei[E + e];
    int p = atomicAdd(&g_cur[dst], 1);
    g_csr[p] = src | (et[e] << 17) | (nt[src] << 19);
}

// ---------------- weight pre-split + stats zero ----------------
__global__ void k_wsplit(const float* __restrict__ W1, const float* __restrict__ W2,
                         const float* __restrict__ hW1, const float* __restrict__ hW2) {
    int idx = blockIdx.x * blockDim.x + threadIdx.x;
    if (idx < 3 * D) { g_sum[idx] = 0.f; g_ss[idx] = 0.f; }
    if (idx >= 8 * 128 * 64) return;
    int w = idx >> 13;
    int n = (idx >> 6) & 127;
    int i = idx & 63;
    const float* W;
    if (w < 6) W = ((w & 1) ? W2 : W1) + (w >> 1) * D * D;
    else W = (w == 6) ? hW1 : hW2;
    float v0 = W[(2 * i) * D + n];
    float v1 = W[(2 * i + 1) * D + n];
    uint32_t h, l;
    bf16_split2(v0, v1, h, l);
    g_wh[idx] = h;
    g_wl[idx] = l;
}

// ---------------- shared GEMM pieces ----------------
#define SWPAD 68
#define GEMM_SMEM ((64 + 64 + 128 + 128) * SWPAD * 4)   // Ahi, Alo, Whs, Wls

__device__ __forceinline__ void mlp_mainloop(const uint32_t* Ahi, const uint32_t* Alo,
                                             const uint32_t* Whs, const uint32_t* Wls,
                                             float acc[2][4][4],
                                             int wr, int wc, int lr, int lc) {
#pragma unroll
    for (int s = 0; s < 8; s++) {
        int kp = 8 * s + lc;
        uint32_t ah[2][4], al[2][4];
#pragma unroll
        for (int m = 0; m < 2; m++) {
            int r0 = (wr + m * 16 + lr) * SWPAD;
            int r1 = r0 + 8 * SWPAD;
            ah[m][0] = Ahi[r0 + kp];
            ah[m][1] = Ahi[r1 + kp];
            ah[m][2] = Ahi[r0 + kp + 4];
            ah[m][3] = Ahi[r1 + kp + 4];
            al[m][0] = Alo[r0 + kp];
            al[m][1] = Alo[r1 + kp];
            al[m][2] = Alo[r0 + kp + 4];
            al[m][3] = Alo[r1 + kp + 4];
        }
        uint32_t bh[4][2], bl[4][2];
#pragma unroll
        for (int n = 0; n < 4; n++) {
            int col = (wc + n * 8 + lr) * SWPAD + kp;
            bh[n][0] = Whs[col];
            bh[n][1] = Whs[col + 4];
            bl[n][0] = Wls[col];
            bl[n][1] = Wls[col + 4];
        }
#pragma unroll
        for (int m = 0; m < 2; m++)
#pragma unroll
            for (int n = 0; n < 4; n++) {
                mma16(acc[m][n], ah[m], bh[n]);
                mma16(acc[m][n], ah[m], bl[n]);
                mma16(acc[m][n], al[m], bh[n]);
            }
    }
}

__device__ __forceinline__ void stage_w(uint32_t* Whs, uint32_t* Wls, int wIdx, int tid) {
    const uint32_t* wh = g_wh + wIdx * 8192;
    const uint32_t* wl = g_wl + wIdx * 8192;
    for (int j = tid; j < 8192; j += 256) {
        int nrow = j >> 6, i = j & 63;
        Whs[nrow * SWPAD + i] = wh[j];
        Wls[nrow * SWPAD + i] = wl[j];
    }
}

// ---------------- fused GINE layer: gather+combine staged straight into MLP ----------------
// MODE 0: source feats = node_emb[node_type] in regs. MODE 1: gather g-buf with BN-apply.
// Then C = (relu(A@WA+bA))@WB + bB  written to out buf (pre-BN), + column stats.
template <int MODE>
__global__ void __launch_bounds__(256, 2) k_fused(
        int aSel, int cSel, int wIdxA, int wIdxB,
        const float* __restrict__ bA, const float* __restrict__ bB, int M,
        int statsOut, int statsIn,
        const float* __restrict__ gamma, const float* __restrict__ beta,
        const float* __restrict__ eemb, const float* __restrict__ epsv, int l,
        const int* __restrict__ nt, const float* __restrict__ nemb) {
    extern __shared__ uint32_t smu[];
    uint32_t* Ahi = smu;                       // [64][SWPAD]
    uint32_t* Alo = Ahi + 64 * SWPAD;
    uint32_t* Whs = Alo + 64 * SWPAD;          // [128][SWPAD]
    uint32_t* Wls = Whs + 128 * SWPAD;

    const float* Ap = bufsel(aSel);
    float* C = bufsel(cSel);

    int tid = threadIdx.x;
    int wid = tid >> 5;
    int lane = tid & 31;
    int row0 = blockIdx.x * 64;

    stage_w(Whs, Wls, wIdxA, tid);

    // per-lane constants
    float4 e0 = *(const float4*)&eemb[lane * 4];
    float4 e1 = *(const float4*)&eemb[D + lane * 4];
    float4 e2 = *(const float4*)&eemb[2 * D + lane * 4];
    float ep = 1.f + epsv[l];
    float s1[4], s2[4];
    float4 nr0, nr1, nr2, nr3;
    if (MODE == 0) {
        nr0 = *(const float4*)&nemb[lane * 4];
        nr1 = *(const float4*)&nemb[D + lane * 4];
        nr2 = *(const float4*)&nemb[2 * D + lane * 4];
        nr3 = *(const float4*)&nemb[3 * D + lane * 4];
    } else {
        float invM = 1.f / (float)M;
        int sb = statsIn * D;
#pragma unroll
        for (int c = 0; c < 4; c++) {
            int f = lane * 4 + c;
            float mu = g_sum[sb + f] * invM;
            float var = g_ss[sb + f] * invM - mu * mu;
            float a = gamma[f] * rsqrtf(var + 1e-5f);
            s1[c] = a;
            s2[c] = beta[f] - mu * a;
        }
    }

#define NSEL(T) ((T) == 0 ? nr0 : (T) == 1 ? nr1 : (T) == 2 ? nr2 : nr3)
#define GETV(V, P) do { \
        if (MODE == 0) { int tn = ((P) >> 19) & 3; V = NSEL(tn); } \
        else { \
            V = *(const float4*)&Ap[(size_t)((P) & 0x1FFFF) * D + lane * 4]; \
            V.x = fmaxf(V.x * s1[0] + s2[0], 0.f); \
            V.y = fmaxf(V.y * s1[1] + s2[1], 0.f); \
            V.z = fmaxf(V.z * s1[2] + s2[2], 0.f); \
            V.w = fmaxf(V.w * s1[3] + s2[3], 0.f); } } while (0)
#define ACCE(A, V, P) do { \
        int te = ((P) >> 17) & 3; \
        float4 ev = (te == 0) ? e0 : (te == 1) ? e1 : e2; \
        A.x += fmaxf(V.x + ev.x, 0.f); \
        A.y += fmaxf(V.y + ev.y, 0.f); \
        A.z += fmaxf(V.z + ev.z, 0.f); \
        A.w += fmaxf(V.w + ev.w, 0.f); } while (0)

    // gather+combine 8 nodes per warp, write pre-split into Ahi/Alo
    for (int r8 = 0; r8 < 8; r8++) {
        int r = wid * 8 + r8;
        int node = row0 + r;
        float4 o = make_float4(0.f, 0.f, 0.f, 0.f);
        if (node < M) {
            float4 a0 = make_float4(0.f, 0.f, 0.f, 0.f);
            float4 a1 = make_float4(0.f, 0.f, 0.f, 0.f);
            float4 a2 = make_float4(0.f, 0.f, 0.f, 0.f);
            float4 a3 = make_float4(0.f, 0.f, 0.f, 0.f);
            int s = g_off[node], e = g_off[node + 1];
            for (int base = s; base < e; base += 32) {
                int cnt = min(32, e - base);
                int p = (lane < cnt) ? g_csr[base + lane] : 0;
                int j = 0;
                for (; j + 3 < cnt; j += 4) {
                    int p0 = __shfl_sync(0xFFFFFFFFu, p, j);
                    int p1 = __shfl_sync(0xFFFFFFFFu, p, j + 1);
                    int p2 = __shfl_sync(0xFFFFFFFFu, p, j + 2);
                    int p3 = __shfl_sync(0xFFFFFFFFu, p, j + 3);
                    float4 v0, v1, v2, v3;
                    GETV(v0, p0); GETV(v1, p1); GETV(v2, p2); GETV(v3, p3);
                    ACCE(a0, v0, p0);
                    ACCE(a1, v1, p1);
                    ACCE(a2, v2, p2);
                    ACCE(a3, v3, p3);
                }
                for (; j < cnt; j++) {
                    int p0 = __shfl_sync(0xFFFFFFFFu, p, j);
                    float4 v0;
                    GETV(v0, p0);
                    ACCE(a0, v0, p0);
                }
            }
            float4 xm;
            if (MODE == 0) {
                int tn = nt[node];
                xm = NSEL(tn);
            } else {
                xm = *(const float4*)&Ap[(size_t)node * D + lane * 4];
                xm.x = fmaxf(xm.x * s1[0] + s2[0], 0.f);
                xm.y = fmaxf(xm.y * s1[1] + s2[1], 0.f);
                xm.z = fmaxf(xm.z * s1[2] + s2[2], 0.f);
                xm.w = fmaxf(xm.w * s1[3] + s2[3], 0.f);
            }
            o.x = ep * xm.x + (a0.x + a1.x) + (a2.x + a3.x);
            o.y = ep * xm.y + (a0.y + a1.y) + (a2.y + a3.y);
            o.z = ep * xm.z + (a0.z + a1.z) + (a2.z + a3.z);
            o.w = ep * xm.w + (a0.w + a1.w) + (a2.w + a3.w);
        }
        uint32_t h0, l0, h1, l1;
        bf16_split2(o.x, o.y, h0, l0);
        bf16_split2(o.z, o.w, h1, l1);
        int base = r * SWPAD + 2 * lane;
        Ahi[base] = h0; Ahi[base + 1] = h1;
        Alo[base] = l0; Alo[base + 1] = l1;
    }
#undef ACCE
#undef GETV
#undef NSEL
    __syncthreads();

    const int wr = (wid & 1) * 32;
    const int wc = (wid >> 1) * 32;
    const int lr = lane >> 2;
    const int lc = lane & 3;

    float acc[2][4][4];
#pragma unroll
    for (int m = 0; m < 2; m++)
#pragma unroll
        for (int n = 0; n < 4; n++)
#pragma unroll
            for (int q = 0; q < 4; q++) acc[m][n][q] = 0.f;

    mlp_mainloop(Ahi, Alo, Whs, Wls, acc, wr, wc, lr, lc);
    __syncthreads();

    // C1 = relu(acc + bA), pre-split -> Ahi/Alo ; restage WB
#pragma unroll
    for (int m = 0; m < 2; m++) {
        int rl = wr + m * 16 + lr;
#pragma unroll
        for (int n = 0; n < 4; n++) {
            int col = wc + n * 8 + lc * 2;
            int cp = col >> 1;
            float bx = bA[col], by = bA[col + 1];
            float x0 = fmaxf(acc[m][n][0] + bx, 0.f);
            float y0 = fmaxf(acc[m][n][1] + by, 0.f);
            float x1 = fmaxf(acc[m][n][2] + bx, 0.f);
            float y1 = fmaxf(acc[m][n][3] + by, 0.f);
            uint32_t h, l;
            bf16_split2(x0, y0, h, l);
            Ahi[rl * SWPAD + cp] = h;
            Alo[rl * SWPAD + cp] = l;
            bf16_split2(x1, y1, h, l);
            Ahi[(rl + 8) * SWPAD + cp] = h;
            Alo[(rl + 8) * SWPAD + cp] = l;
        }
    }
    stage_w(Whs, Wls, wIdxB, tid);
    __syncthreads();

#pragma unroll
    for (int m = 0; m < 2; m++)
#pragma unroll
        for (int n = 0; n < 4; n++)
#pragma unroll
            for (int q = 0; q < 4; q++) acc[m][n][q] = 0.f;

    mlp_mainloop(Ahi, Alo, Whs, Wls, acc, wr, wc, lr, lc);

    // epilogue: h = acc + bB (no relu; BN later) + column stats
    float ps[4][2], pss[4][2];
#pragma unroll
    for (int n = 0; n < 4; n++)
#pragma unroll
        for (int q = 0; q < 2; q++) { ps[n][q] = 0.f; pss[n][q] = 0.f; }

#pragma unroll
    for (int m = 0; m < 2; m++) {
        int row = row0 + wr + m * 16 + lr;
#pragma unroll
        for (int n = 0; n < 4; n++) {
            int col = wc + n * 8 + lc * 2;
            float bx = bB[col], by = bB[col + 1];
            if (row < M) {
                float ox = acc[m][n][0] + bx;
                float oy = acc[m][n][1] + by;
                ps[n][0] += ox; pss[n][0] += ox * ox;
                ps[n][1] += oy; pss[n][1] += oy * oy;
                *(float2*)&C[(size_t)row * D + col] = make_float2(ox, oy);
            }
            if (row + 8 < M) {
                float ox = acc[m][n][2] + bx;
                float oy = acc[m][n][3] + by;
                ps[n][0] += ox; pss[n][0] += ox * ox;
                ps[n][1] += oy; pss[n][1] += oy * oy;
                *(float2*)&C[(size_t)(row + 8) * D + col] = make_float2(ox, oy);
            }
        }
    }

    {
        int sb = statsOut * D;
#pragma unroll
        for (int n = 0; n < 4; n++)
#pragma unroll
            for (int q = 0; q < 2; q++) {
#pragma unroll
                for (int off = 4; off < 32; off <<= 1) {
                    ps[n][q]  += __shfl_xor_sync(0xFFFFFFFFu, ps[n][q], off);
                    pss[n][q] += __shfl_xor_sync(0xFFFFFFFFu, pss[n][q], off);
                }
            }
        if (lr == 0) {
#pragma unroll
            for (int n = 0; n < 4; n++) {
                int col = wc + n * 8 + lc * 2;
                atomicAdd(&g_sum[sb + col], ps[n][0]);
                atomicAdd(&g_sum[sb + col + 1], ps[n][1]);
                atomicAdd(&g_ss[sb + col], pss[n][0]);
                atomicAdd(&g_ss[sb + col + 1], pss[n][1]);
            }
        }
    }
}

// ---------------- head: BN(statsIn)+relu at staging, 2-GEMM MLP, fused final dot ----------------
__global__ void __launch_bounds__(256, 2) k_head(
        int aSel, int wIdxA, int wIdxB,
        const float* __restrict__ bA, const float* __restrict__ bB, int M,
        int statsIn,
        const float* __restrict__ gamma, const float* __restrict__ beta,
        const float* __restrict__ w3, const float* __restrict__ b3,
        float* __restrict__ out) {
    extern __shared__ uint32_t smu[];
    uint32_t* Ahi = smu;
    uint32_t* Alo = Ahi + 64 * SWPAD;
    uint32_t* Whs = Alo + 64 * SWPAD;
    uint32_t* Wls = Whs + 128 * SWPAD;
    __shared__ float s1sh[128];
    __shared__ float s2sh[128];

    const float* A = bufsel(aSel);
    int tid = threadIdx.x;
    int wid = tid >> 5;
    int lane = tid & 31;
    int row0 = blockIdx.x * 64;

    if (tid < 128) {
        float invM = 1.f / (float)M;
        int sb = statsIn * D;
        float mu = g_sum[sb + tid] * invM;
        float var = g_ss[sb + tid] * invM - mu * mu;
        float a = gamma[tid] * rsqrtf(var + 1e-5f);
        s1sh[tid] = a;
        s2sh[tid] = beta[tid] - mu * a;
    }
    __syncthreads();

    for (int i = tid; i < 2048; i += 256) {
        int r = i >> 5, q = i & 31;
        int gr = row0 + r;
        float4 v = make_float4(0.f, 0.f, 0.f, 0.f);
        if (gr < M) {
            v = *(const float4*)&A[(size_t)gr * D + q * 4];
            int f = q * 4;
            v.x = fmaxf(v.x * s1sh[f] + s2sh[f], 0.f);
            v.y = fmaxf(v.y * s1sh[f + 1] + s2sh[f + 1], 0.f);
            v.z = fmaxf(v.z * s1sh[f + 2] + s2sh[f + 2], 0.f);
            v.w = fmaxf(v.w * s1sh[f + 3] + s2sh[f + 3], 0.f);
        }
        uint32_t h0, l0, h1, l1;
        bf16_split2(v.x, v.y, h0, l0);
        bf16_split2(v.z, v.w, h1, l1);
        int base = r * SWPAD + 2 * q;
        Ahi[base] = h0; Ahi[base + 1] = h1;
        Alo[base] = l0; Alo[base + 1] = l1;
    }
    stage_w(Whs, Wls, wIdxA, tid);
    __syncthreads();

    const int wr = (wid & 1) * 32;
    const int wc = (wid >> 1) * 32;
    const int lr = lane >> 2;
    const int lc = lane & 3;

    float acc[2][4][4];
#pragma unroll
    for (int m = 0; m < 2; m++)
#pragma unroll
        for (int n = 0; n < 4; n++)
#pragma unroll
            for (int q = 0; q < 4; q++) acc[m][n][q] = 0.f;

    mlp_mainloop(Ahi, Alo, Whs, Wls, acc, wr, wc, lr, lc);
    __syncthreads();

#pragma unroll
    for (int m = 0; m < 2; m++) {
        int rl = wr + m * 16 + lr;
#pragma unroll
        for (int n = 0; n < 4; n++) {
            int col = wc + n * 8 + lc * 2;
            int cp = col >> 1;
            float bx = bA[col], by = bA[col + 1];
            float x0 = fmaxf(acc[m][n][0] + bx, 0.f);
            float y0 = fmaxf(acc[m][n][1] + by, 0.f);
            float x1 = fmaxf(acc[m][n][2] + bx, 0.f);
            float y1 = fmaxf(acc[m][n][3] + by, 0.f);
            uint32_t h, l;
            bf16_split2(x0, y0, h, l);
            Ahi[rl * SWPAD + cp] = h;
            Alo[rl * SWPAD + cp] = l;
            bf16_split2(x1, y1, h, l);
            Ahi[(rl + 8) * SWPAD + cp] = h;
            Alo[(rl + 8) * SWPAD + cp] = l;
        }
    }
    stage_w(Whs, Wls, wIdxB, tid);
    __syncthreads();

#pragma unroll
    for (int m = 0; m < 2; m++)
#pragma unroll
        for (int n = 0; n < 4; n++)
#pragma unroll
            for (int q = 0; q < 4; q++) acc[m][n][q] = 0.f;

    mlp_mainloop(Ahi, Alo, Whs, Wls, acc, wr, wc, lr, lc);
    __syncthreads();

    // C2 = relu(acc + bB) into SMEM (reuse W buffers), dot with w3
    float* Cs = (float*)Whs;   // [64][132]
#pragma unroll
    for (int m = 0; m < 2; m++) {
        int rl = wr + m * 16 + lr;
#pragma unroll
        for (int n = 0; n < 4; n++) {
            int col = wc + n * 8 + lc * 2;
            float bx = bB[col], by = bB[col + 1];
            float2 o0, o1;
            o0.x = fmaxf(acc[m][n][0] + bx, 0.f);
            o0.y = fmaxf(acc[m][n][1] + by, 0.f);
            o1.x = fmaxf(acc[m][n][2] + bx, 0.f);
            o1.y = fmaxf(acc[m][n][3] + by, 0.f);
            *(float2*)&Cs[rl * 132 + col] = o0;
            *(float2*)&Cs[(rl + 8) * 132 + col] = o1;
        }
    }
    __syncthreads();
    float4 w = *(const float4*)&w3[lane * 4];
    float bias3 = b3[0];
#pragma unroll
    for (int r8 = 0; r8 < 8; r8++) {
        int row = wid * 8 + r8;
        float4 a = *(const float4*)&Cs[row * 132 + lane * 4];
        float s = a.x * w.x + a.y * w.y + a.z * w.z + a.w * w.w;
#pragma unroll
        for (int o = 16; o > 0; o >>= 1)
            s += __shfl_down_sync(0xFFFFFFFFu, s, o);
        if (lane == 0 && row0 + row < M)
            out[row0 + row] = s + bias3;
    }
}

// ---------------- launcher ----------------
extern "C" void kernel_launch(void* const* d_in, const int* in_sizes, int n_in,
                              void* d_out, int out_size) {
    const int*   node_type  = (const int*)  d_in[0];
    const int*   edge_type  = (const int*)  d_in[1];
    const int*   edge_index = (const int*)  d_in[2];
    const float* node_emb   = (const float*)d_in[3];
    const float* edge_emb   = (const float*)d_in[4];
    const float* eps        = (const float*)d_in[5];
    const float* W1         = (const float*)d_in[6];
    const float* b1         = (const float*)d_in[7];
    const float* W2         = (const float*)d_in[8];
    const float* b2         = (const float*)d_in[9];
    const float* gamma      = (const float*)d_in[10];
    const float* beta       = (const float*)d_in[11];
    const float* hW1        = (const float*)d_in[12];
    const float* hb1        = (const float*)d_in[13];
    const float* hW2        = (const float*)d_in[14];
    const float* hb2        = (const float*)d_in[15];
    const float* hW3        = (const float*)d_in[16];
    const float* hb3        = (const float*)d_in[17];
    float* out = (float*)d_out;

    int N = in_sizes[0];
    int E = in_sizes[1];
    int nb = (N + 255) / 256;
    int gTiles = (N + 63) / 64;

    static int smemSet = 0;
    if (!smemSet) {
        cudaFuncSetAttribute(k_fused<0>, cudaFuncAttributeMaxDynamicSharedMemorySize, GEMM_SMEM);
        cudaFuncSetAttribute(k_fused<1>, cudaFuncAttributeMaxDynamicSharedMemorySize, GEMM_SMEM);
        cudaFuncSetAttribute(k_head, cudaFuncAttributeMaxDynamicSharedMemorySize, GEMM_SMEM);
        smemSet = 1;
    }

    // CSR build (multi-block scan)
    k_zero_deg<<<nb, 256>>>(N);
    k_hist<<<(E + 255) / 256, 256>>>(edge_index, E);
    k_scan_partial<<<nb, 256>>>(N);
    k_scan_part<<<1, 256>>>(nb);
    k_scan_write<<<nb, 256>>>(N, E);
    k_fill<<<(E + 255) / 256, 256>>>(edge_index, edge_type, node_type, E);

    // weight pre-split (+ zero all per-layer stats)
    k_wsplit<<<(8 * 128 * 64 + 255) / 256, 256>>>(W1, W2, hW1, hW2);

    // fused layers: gather(+embed / +BN-of-prev) -> MLP -> h(+stats). buffers ping-pong.
    // layer0: -> buf0 ; layer1: buf0 -> buf1 ; layer2: buf1 -> buf0 ; head: buf0 -> out
    k_fused<0><<<gTiles, 256, GEMM_SMEM>>>(0, 0, 0, 1, b1, b2, N,
                                           0, -1, nullptr, nullptr,
                                           edge_emb, eps, 0, node_type, node_emb);
    k_fused<1><<<gTiles, 256, GEMM_SMEM>>>(0, 1, 2, 3, b1 + D, b2 + D, N,
                                           1, 0, gamma, beta,
                                           edge_emb, eps, 1, nullptr, nullptr);
    k_fused<1><<<gTiles, 256, GEMM_SMEM>>>(1, 0, 4, 5, b1 + 2 * D, b2 + 2 * D, N,
                                           2, 1, gamma + D, beta + D,
                                           edge_emb, eps, 2, nullptr, nullptr);
    k_head<<<gTiles, 256, GEMM_SMEM>>>(0, 6, 7, hb1, hb2, N,
                                       2, gamma + 2 * D, beta + 2 * D,
                                       hW3, hb3, out);
}

// round 13
// speedup vs baseline: 2.6414x; 1.0473x over previous
#include <cuda_runtime.h>
#include <cstdint>

#define NN 50000
#define EE 800000
#define D  128
#define L  3

// ---------------- scratch (device globals; no allocation APIs) ----------------
__device__ float g_x [NN * D];              // ping-pong activation buffers
__device__ float g_h [NN * D];
__device__ int   g_deg[NN];
__device__ int   g_off[NN + 1];
__device__ int   g_cur[NN];
__device__ int   g_csr[EE];                 // packed: src | et<<17 | nt(src)<<19
__device__ float g_sum[3 * D];              // per-layer BN stats
__device__ float g_ss [3 * D];
__device__ uint32_t g_wh[8 * 128 * 64];     // W split hi: [w][n][kpair] bf16x2
__device__ uint32_t g_wl[8 * 128 * 64];     // W split lo
__device__ int g_ticket;                    // decoupled-lookback scan state
__device__ unsigned long long g_scanstate[64];

__device__ __forceinline__ float* bufsel(int s) {
    return s == 0 ? g_x : g_h;
}

// pack two floats into bf16x2 (v0 low half / v1 high half) + residual pair
__device__ __forceinline__ void bf16_split2(float v0, float v1, uint32_t& hi, uint32_t& lo) {
    uint32_t h;
    asm("cvt.rn.bf16x2.f32 %0, %1, %2;" : "=r"(h) : "f"(v1), "f"(v0));
    float h0 = __uint_as_float(h << 16);
    float h1 = __uint_as_float(h & 0xFFFF0000u);
    float r0 = v0 - h0;
    float r1 = v1 - h1;
    uint32_t l;
    asm("cvt.rn.bf16x2.f32 %0, %1, %2;" : "=r"(l) : "f"(r1), "f"(r0));
    hi = h; lo = l;
}

__device__ __forceinline__ void mma16(float* c, const uint32_t* a, const uint32_t* b) {
    asm volatile("mma.sync.aligned.m16n8k16.row.col.f32.bf16.bf16.f32 "
                 "{%0,%1,%2,%3}, {%4,%5,%6,%7}, {%8,%9}, {%0,%1,%2,%3};"
                 : "+f"(c[0]), "+f"(c[1]), "+f"(c[2]), "+f"(c[3])
                 : "r"(a[0]), "r"(a[1]), "r"(a[2]), "r"(a[3]), "r"(b[0]), "r"(b[1]));
}

// ---------------- weight pre-split + all-state zero (runs FIRST) ----------------
__global__ void k_wsplit(const float* __restrict__ W1, const float* __restrict__ W2,
                         const float* __restrict__ hW1, const float* __restrict__ hW2,
                         int n) {
    int idx = blockIdx.x * blockDim.x + threadIdx.x;
    if (idx < n) g_deg[idx] = 0;
    if (idx < 3 * D) { g_sum[idx] = 0.f; g_ss[idx] = 0.f; }
    if (idx < 64) g_scanstate[idx] = 0ull;
    if (idx == 0) g_ticket = 0;
    if (idx >= 8 * 128 * 64) return;
    int w = idx >> 13;
    int nn = (idx >> 6) & 127;
    int i = idx & 63;
    const float* W;
    if (w < 6) W = ((w & 1) ? W2 : W1) + (w >> 1) * D * D;
    else W = (w == 6) ? hW1 : hW2;
    float v0 = W[(2 * i) * D + nn];
    float v1 = W[(2 * i + 1) * D + nn];
    uint32_t h, l;
    bf16_split2(v0, v1, h, l);
    g_wh[idx] = h;
    g_wl[idx] = l;
}

// ---------------- CSR build ----------------
__global__ void k_hist(const int* __restrict__ ei, int E) {
    int e = blockIdx.x * blockDim.x + threadIdx.x;
    if (e < E) atomicAdd(&g_deg[ei[E + e]], 1);
}

// single-pass decoupled-lookback exclusive scan: g_deg -> g_off, g_cur
// 256 threads x 4 items = 1024 elements per block.
__global__ void __launch_bounds__(256) k_scan_lb(int n, int E) {
    __shared__ int sbid;
    __shared__ int wsum[8];
    __shared__ int btot;
    __shared__ int sprefix;
    int t = threadIdx.x;
    int lane = t & 31, w = t >> 5;
    if (t == 0) sbid = atomicAdd(&g_ticket, 1);
    __syncthreads();
    int bid = sbid;
    int idx0 = bid * 1024 + t * 4;

    int v[4];
#pragma unroll
    for (int i = 0; i < 4; i++) v[i] = (idx0 + i < n) ? g_deg[idx0 + i] : 0;
    int tsum = v[0] + v[1] + v[2] + v[3];

    int s = tsum;
#pragma unroll
    for (int o = 1; o < 32; o <<= 1) {
        int x = __shfl_up_sync(0xFFFFFFFFu, s, o);
        if (lane >= o) s += x;
    }
    if (lane == 31) wsum[w] = s;
    __syncthreads();
    if (w == 0 && lane < 8) {
        int x = wsum[lane];
        int ss = x;
#pragma unroll
        for (int o = 1; o < 8; o <<= 1) {
            int y = __shfl_up_sync(0xFFu, ss, o);
            if (lane >= o) ss += y;
        }
        wsum[lane] = ss - x;
    }
    __syncthreads();
    int exclBlk = wsum[w] + s - tsum;
    if (t == 255) btot = exclBlk + tsum;
    __syncthreads();

    if (t == 0) {
        unsigned long long pkt = ((bid == 0) ? (2ull << 32) : (1ull << 32))
                               | (unsigned long long)(unsigned)btot;
        atomicExch(&g_scanstate[bid], pkt);
    }
    int prefix = 0;
    if (bid > 0) {
        if (t == 0) {
            int acc = 0;
            int j = bid - 1;
            while (true) {
                unsigned long long pkt;
                do { pkt = atomicAdd(&g_scanstate[j], 0ull); } while ((pkt >> 32) == 0ull);
                acc += (int)(unsigned)pkt;
                if ((pkt >> 32) == 2ull) break;
                j--;
            }
            sprefix = acc;
            atomicExch(&g_scanstate[bid],
                       (2ull << 32) | (unsigned long long)(unsigned)(acc + btot));
        }
        __syncthreads();
        prefix = sprefix;
    }

    int run = prefix + exclBlk;
#pragma unroll
    for (int i = 0; i < 4; i++) {
        int idx = idx0 + i;
        if (idx < n) { g_off[idx] = run; g_cur[idx] = run; }
        run += v[i];
    }
    if (bid == 0 && t == 0) g_off[n] = E;
}

// fill also packs node_type[src] (2 bits) so layer-0 gather needs no feature loads
__global__ void k_fill(const int* __restrict__ ei, const int* __restrict__ et,
                       const int* __restrict__ nt, int E) {
    int e = blockIdx.x * blockDim.x + threadIdx.x;
    if (e >= E) return;
    int src = ei[e];
    int dst = ei[E + e];
    int p = atomicAdd(&g_cur[dst], 1);
    g_csr[p] = src | (et[e] << 17) | (nt[src] << 19);
}

// ---------------- shared GEMM pieces ----------------
#define SWPAD 68
#define GEMM_SMEM ((64 + 64 + 128 + 128) * SWPAD * 4)   // Ahi, Alo, Whs, Wls

__device__ __forceinline__ void mlp_mainloop(const uint32_t* Ahi, const uint32_t* Alo,
                                             const uint32_t* Whs, const uint32_t* Wls,
                                             float acc[2][4][4],
                                             int wr, int wc, int lr, int lc) {
#pragma unroll
    for (int s = 0; s < 8; s++) {
        int kp = 8 * s + lc;
        uint32_t ah[2][4], al[2][4];
#pragma unroll
        for (int m = 0; m < 2; m++) {
            int r0 = (wr + m * 16 + lr) * SWPAD;
            int r1 = r0 + 8 * SWPAD;
            ah[m][0] = Ahi[r0 + kp];
            ah[m][1] = Ahi[r1 + kp];
            ah[m][2] = Ahi[r0 + kp + 4];
            ah[m][3] = Ahi[r1 + kp + 4];
            al[m][0] = Alo[r0 + kp];
            al[m][1] = Alo[r1 + kp];
            al[m][2] = Alo[r0 + kp + 4];
            al[m][3] = Alo[r1 + kp + 4];
        }
        uint32_t bh[4][2], bl[4][2];
#pragma unroll
        for (int n = 0; n < 4; n++) {
            int col = (wc + n * 8 + lr) * SWPAD + kp;
            bh[n][0] = Whs[col];
            bh[n][1] = Whs[col + 4];
            bl[n][0] = Wls[col];
            bl[n][1] = Wls[col + 4];
        }
#pragma unroll
        for (int m = 0; m < 2; m++)
#pragma unroll
            for (int n = 0; n < 4; n++) {
                mma16(acc[m][n], ah[m], bh[n]);
                mma16(acc[m][n], ah[m], bl[n]);
                mma16(acc[m][n], al[m], bh[n]);
            }
    }
}

__device__ __forceinline__ void stage_w(uint32_t* Whs, uint32_t* Wls, int wIdx, int tid) {
    const uint32_t* wh = g_wh + wIdx * 8192;
    const uint32_t* wl = g_wl + wIdx * 8192;
    for (int j = tid; j < 8192; j += 256) {
        int nrow = j >> 6, i = j & 63;
        Whs[nrow * SWPAD + i] = wh[j];
        Wls[nrow * SWPAD + i] = wl[j];
    }
}

// ---------------- fused GINE layer: gather+combine staged straight into MLP ----------------
// MODE 0: source feats = node_emb[node_type] in regs. MODE 1: gather g-buf with BN-apply.
// Then C = (relu(A@WA+bA))@WB + bB  written to out buf (pre-BN), + column stats.
template <int MODE>
__global__ void __launch_bounds__(256, 2) k_fused(
        int aSel, int cSel, int wIdxA, int wIdxB,
        const float* __restrict__ bA, const float* __restrict__ bB, int M,
        int statsOut, int statsIn,
        const float* __restrict__ gamma, const float* __restrict__ beta,
        const float* __restrict__ eemb, const float* __restrict__ epsv, int l,
        const int* __restrict__ nt, const float* __restrict__ nemb) {
    extern __shared__ uint32_t smu[];
    uint32_t* Ahi = smu;                       // [64][SWPAD]
    uint32_t* Alo = Ahi + 64 * SWPAD;
    uint32_t* Whs = Alo + 64 * SWPAD;          // [128][SWPAD]
    uint32_t* Wls = Whs + 128 * SWPAD;

    const float* Ap = bufsel(aSel);
    float* C = bufsel(cSel);

    int tid = threadIdx.x;
    int wid = tid >> 5;
    int lane = tid & 31;
    int row0 = blockIdx.x * 64;

    stage_w(Whs, Wls, wIdxA, tid);

    // per-lane constants
    float4 e0 = *(const float4*)&eemb[lane * 4];
    float4 e1 = *(const float4*)&eemb[D + lane * 4];
    float4 e2 = *(const float4*)&eemb[2 * D + lane * 4];
    float ep = 1.f + epsv[l];
    float s1[4], s2[4];
    float4 nr0, nr1, nr2, nr3;
    if (MODE == 0) {
        nr0 = *(const float4*)&nemb[lane * 4];
        nr1 = *(const float4*)&nemb[D + lane * 4];
        nr2 = *(const float4*)&nemb[2 * D + lane * 4];
        nr3 = *(const float4*)&nemb[3 * D + lane * 4];
    } else {
        float invM = 1.f / (float)M;
        int sb = statsIn * D;
#pragma unroll
        for (int c = 0; c < 4; c++) {
            int f = lane * 4 + c;
            float mu = g_sum[sb + f] * invM;
            float var = g_ss[sb + f] * invM - mu * mu;
            float a = gamma[f] * rsqrtf(var + 1e-5f);
            s1[c] = a;
            s2[c] = beta[f] - mu * a;
        }
    }

#define NSEL(T) ((T) == 0 ? nr0 : (T) == 1 ? nr1 : (T) == 2 ? nr2 : nr3)
#define GETV(V, P) do { \
        if (MODE == 0) { int tn = ((P) >> 19) & 3; V = NSEL(tn); } \
        else { \
            V = *(const float4*)&Ap[(size_t)((P) & 0x1FFFF) * D + lane * 4]; \
            V.x = fmaxf(V.x * s1[0] + s2[0], 0.f); \
            V.y = fmaxf(V.y * s1[1] + s2[1], 0.f); \
            V.z = fmaxf(V.z * s1[2] + s2[2], 0.f); \
            V.w = fmaxf(V.w * s1[3] + s2[3], 0.f); } } while (0)
#define ACCE(A, V, P) do { \
        int te = ((P) >> 17) & 3; \
        float4 ev = (te == 0) ? e0 : (te == 1) ? e1 : e2; \
        A.x += fmaxf(V.x + ev.x, 0.f); \
        A.y += fmaxf(V.y + ev.y, 0.f); \
        A.z += fmaxf(V.z + ev.z, 0.f); \
        A.w += fmaxf(V.w + ev.w, 0.f); } while (0)

    // gather+combine 8 nodes per warp (8-way edge unroll), write pre-split into Ahi/Alo
    for (int r8 = 0; r8 < 8; r8++) {
        int r = wid * 8 + r8;
        int node = row0 + r;
        float4 o = make_float4(0.f, 0.f, 0.f, 0.f);
        if (node < M) {
            float4 a0 = make_float4(0.f, 0.f, 0.f, 0.f);
            float4 a1 = make_float4(0.f, 0.f, 0.f, 0.f);
            float4 a2 = make_float4(0.f, 0.f, 0.f, 0.f);
            float4 a3 = make_float4(0.f, 0.f, 0.f, 0.f);
            int s = g_off[node], e = g_off[node + 1];
            for (int base = s; base < e; base += 32) {
                int cnt = min(32, e - base);
                int p = (lane < cnt) ? g_csr[base + lane] : 0;
                int j = 0;
                for (; j + 7 < cnt; j += 8) {
                    int p0 = __shfl_sync(0xFFFFFFFFu, p, j);
                    int p1 = __shfl_sync(0xFFFFFFFFu, p, j + 1);
                    int p2 = __shfl_sync(0xFFFFFFFFu, p, j + 2);
                    int p3 = __shfl_sync(0xFFFFFFFFu, p, j + 3);
                    int p4 = __shfl_sync(0xFFFFFFFFu, p, j + 4);
                    int p5 = __shfl_sync(0xFFFFFFFFu, p, j + 5);
                    int p6 = __shfl_sync(0xFFFFFFFFu, p, j + 6);
                    int p7 = __shfl_sync(0xFFFFFFFFu, p, j + 7);
                    float4 v0, v1, v2, v3, v4, v5, v6, v7;
                    GETV(v0, p0); GETV(v1, p1); GETV(v2, p2); GETV(v3, p3);
                    GETV(v4, p4); GETV(v5, p5); GETV(v6, p6); GETV(v7, p7);
                    ACCE(a0, v0, p0);
                    ACCE(a1, v1, p1);
                    ACCE(a2, v2, p2);
                    ACCE(a3, v3, p3);
                    ACCE(a0, v4, p4);
                    ACCE(a1, v5, p5);
                    ACCE(a2, v6, p6);
                    ACCE(a3, v7, p7);
                }
                for (; j + 3 < cnt; j += 4) {
                    int p0 = __shfl_sync(0xFFFFFFFFu, p, j);
                    int p1 = __shfl_sync(0xFFFFFFFFu, p, j + 1);
                    int p2 = __shfl_sync(0xFFFFFFFFu, p, j + 2);
                    int p3 = __shfl_sync(0xFFFFFFFFu, p, j + 3);
                    float4 v0, v1, v2, v3;
                    GETV(v0, p0); GETV(v1, p1); GETV(v2, p2); GETV(v3, p3);
                    ACCE(a0, v0, p0);
                    ACCE(a1, v1, p1);
                    ACCE(a2, v2, p2);
                    ACCE(a3, v3, p3);
                }
                for (; j < cnt; j++) {
                    int p0 = __shfl_sync(0xFFFFFFFFu, p, j);
                    float4 v0;
                    GETV(v0, p0);
                    ACCE(a0, v0, p0);
                }
            }
            float4 xm;
            if (MODE == 0) {
                int tn = nt[node];
                xm = NSEL(tn);
            } else {
                xm = *(const float4*)&Ap[(size_t)node * D + lane * 4];
                xm.x = fmaxf(xm.x * s1[0] + s2[0], 0.f);
                xm.y = fmaxf(xm.y * s1[1] + s2[1], 0.f);
                xm.z = fmaxf(xm.z * s1[2] + s2[2], 0.f);
                xm.w = fmaxf(xm.w * s1[3] + s2[3], 0.f);
            }
            o.x = ep * xm.x + (a0.x + a1.x) + (a2.x + a3.x);
            o.y = ep * xm.y + (a0.y + a1.y) + (a2.y + a3.y);
            o.z = ep * xm.z + (a0.z + a1.z) + (a2.z + a3.z);
            o.w = ep * xm.w + (a0.w + a1.w) + (a2.w + a3.w);
        }
        uint32_t h0, l0, h1, l1;
        bf16_split2(o.x, o.y, h0, l0);
        bf16_split2(o.z, o.w, h1, l1);
        int base = r * SWPAD + 2 * lane;
        Ahi[base] = h0; Ahi[base + 1] = h1;
        Alo[base] = l0; Alo[base + 1] = l1;
    }
#undef ACCE
#undef GETV
#undef NSEL
    __syncthreads();

    const int wr = (wid & 1) * 32;
    const int wc = (wid >> 1) * 32;
    const int lr = lane >> 2;
    const int lc = lane & 3;

    float acc[2][4][4];
#pragma unroll
    for (int m = 0; m < 2; m++)
#pragma unroll
        for (int n = 0; n < 4; n++)
#pragma unroll
            for (int q = 0; q < 4; q++) acc[m][n][q] = 0.f;

    mlp_mainloop(Ahi, Alo, Whs, Wls, acc, wr, wc, lr, lc);
    __syncthreads();

    // C1 = relu(acc + bA), pre-split -> Ahi/Alo ; restage WB
#pragma unroll
    for (int m = 0; m < 2; m++) {
        int rl = wr + m * 16 + lr;
#pragma unroll
        for (int n = 0; n < 4; n++) {
            int col = wc + n * 8 + lc * 2;
            int cp = col >> 1;
            float bx = bA[col], by = bA[col + 1];
            float x0 = fmaxf(acc[m][n][0] + bx, 0.f);
            float y0 = fmaxf(acc[m][n][1] + by, 0.f);
            float x1 = fmaxf(acc[m][n][2] + bx, 0.f);
            float y1 = fmaxf(acc[m][n][3] + by, 0.f);
            uint32_t h, l;
            bf16_split2(x0, y0, h, l);
            Ahi[rl * SWPAD + cp] = h;
            Alo[rl * SWPAD + cp] = l;
            bf16_split2(x1, y1, h, l);
            Ahi[(rl + 8) * SWPAD + cp] = h;
            Alo[(rl + 8) * SWPAD + cp] = l;
        }
    }
    stage_w(Whs, Wls, wIdxB, tid);
    __syncthreads();

#pragma unroll
    for (int m = 0; m < 2; m++)
#pragma unroll
        for (int n = 0; n < 4; n++)
#pragma unroll
            for (int q = 0; q < 4; q++) acc[m][n][q] = 0.f;

    mlp_mainloop(Ahi, Alo, Whs, Wls, acc, wr, wc, lr, lc);

    // epilogue: h = acc + bB (no relu; BN later) + column stats
    float ps[4][2], pss[4][2];
#pragma unroll
    for (int n = 0; n < 4; n++)
#pragma unroll
        for (int q = 0; q < 2; q++) { ps[n][q] = 0.f; pss[n][q] = 0.f; }

#pragma unroll
    for (int m = 0; m < 2; m++) {
        int row = row0 + wr + m * 16 + lr;
#pragma unroll
        for (int n = 0; n < 4; n++) {
            int col = wc + n * 8 + lc * 2;
            float bx = bB[col], by = bB[col + 1];
            if (row < M) {
                float ox = acc[m][n][0] + bx;
                float oy = acc[m][n][1] + by;
                ps[n][0] += ox; pss[n][0] += ox * ox;
                ps[n][1] += oy; pss[n][1] += oy * oy;
                *(float2*)&C[(size_t)row * D + col] = make_float2(ox, oy);
            }
            if (row + 8 < M) {
                float ox = acc[m][n][2] + bx;
                float oy = acc[m][n][3] + by;
                ps[n][0] += ox; pss[n][0] += ox * ox;
                ps[n][1] += oy; pss[n][1] += oy * oy;
                *(float2*)&C[(size_t)(row + 8) * D + col] = make_float2(ox, oy);
            }
        }
    }

    {
        int sb = statsOut * D;
#pragma unroll
        for (int n = 0; n < 4; n++)
#pragma unroll
            for (int q = 0; q < 2; q++) {
#pragma unroll
                for (int off = 4; off < 32; off <<= 1) {
                    ps[n][q]  += __shfl_xor_sync(0xFFFFFFFFu, ps[n][q], off);
                    pss[n][q] += __shfl_xor_sync(0xFFFFFFFFu, pss[n][q], off);
                }
            }
        if (lr == 0) {
#pragma unroll
            for (int n = 0; n < 4; n++) {
                int col = wc + n * 8 + lc * 2;
                atomicAdd(&g_sum[sb + col], ps[n][0]);
                atomicAdd(&g_sum[sb + col + 1], ps[n][1]);
                atomicAdd(&g_ss[sb + col], pss[n][0]);
                atomicAdd(&g_ss[sb + col + 1], pss[n][1]);
            }
        }
    }
}

// ---------------- head: BN(statsIn)+relu at staging, 2-GEMM MLP, fused final dot ----------------
__global__ void __launch_bounds__(256, 2) k_head(
        int aSel, int wIdxA, int wIdxB,
        const float* __restrict__ bA, const float* __restrict__ bB, int M,
        int statsIn,
        const float* __restrict__ gamma, const float* __restrict__ beta,
        const float* __restrict__ w3, const float* __restrict__ b3,
        float* __restrict__ out) {
    extern __shared__ uint32_t smu[];
    uint32_t* Ahi = smu;
    uint32_t* Alo = Ahi + 64 * SWPAD;
    uint32_t* Whs = Alo + 64 * SWPAD;
    uint32_t* Wls = Whs + 128 * SWPAD;
    __shared__ float s1sh[128];
    __shared__ float s2sh[128];

    const float* A = bufsel(aSel);
    int tid = threadIdx.x;
    int wid = tid >> 5;
    int lane = tid & 31;
    int row0 = blockIdx.x * 64;

    if (tid < 128) {
        float invM = 1.f / (float)M;
        int sb = statsIn * D;
        float mu = g_sum[sb + tid] * invM;
        float var = g_ss[sb + tid] * invM - mu * mu;
        float a = gamma[tid] * rsqrtf(var + 1e-5f);
        s1sh[tid] = a;
        s2sh[tid] = beta[tid] - mu * a;
    }
    __syncthreads();

    for (int i = tid; i < 2048; i += 256) {
        int r = i >> 5, q = i & 31;
        int gr = row0 + r;
        float4 v = make_float4(0.f, 0.f, 0.f, 0.f);
        if (gr < M) {
            v = *(const float4*)&A[(size_t)gr * D + q * 4];
            int f = q * 4;
            v.x = fmaxf(v.x * s1sh[f] + s2sh[f], 0.f);
            v.y = fmaxf(v.y * s1sh[f + 1] + s2sh[f + 1], 0.f);
            v.z = fmaxf(v.z * s1sh[f + 2] + s2sh[f + 2], 0.f);
            v.w = fmaxf(v.w * s1sh[f + 3] + s2sh[f + 3], 0.f);
        }
        uint32_t h0, l0, h1, l1;
        bf16_split2(v.x, v.y, h0, l0);
        bf16_split2(v.z, v.w, h1, l1);
        int base = r * SWPAD + 2 * q;
        Ahi[base] = h0; Ahi[base + 1] = h1;
        Alo[base] = l0; Alo[base + 1] = l1;
    }
    stage_w(Whs, Wls, wIdxA, tid);
    __syncthreads();

    const int wr = (wid & 1) * 32;
    const int wc = (wid >> 1) * 32;
    const int lr = lane >> 2;
    const int lc = lane & 3;

    float acc[2][4][4];
#pragma unroll
    for (int m = 0; m < 2; m++)
#pragma unroll
        for (int n = 0; n < 4; n++)
#pragma unroll
            for (int q = 0; q < 4; q++) acc[m][n][q] = 0.f;

    mlp_mainloop(Ahi, Alo, Whs, Wls, acc, wr, wc, lr, lc);
    __syncthreads();

#pragma unroll
    for (int m = 0; m < 2; m++) {
        int rl = wr + m * 16 + lr;
#pragma unroll
        for (int n = 0; n < 4; n++) {
            int col = wc + n * 8 + lc * 2;
            int cp = col >> 1;
            float bx = bA[col], by = bA[col + 1];
            float x0 = fmaxf(acc[m][n][0] + bx, 0.f);
            float y0 = fmaxf(acc[m][n][1] + by, 0.f);
            float x1 = fmaxf(acc[m][n][2] + bx, 0.f);
            float y1 = fmaxf(acc[m][n][3] + by, 0.f);
            uint32_t h, l;
            bf16_split2(x0, y0, h, l);
            Ahi[rl * SWPAD + cp] = h;
            Alo[rl * SWPAD + cp] = l;
            bf16_split2(x1, y1, h, l);
            Ahi[(rl + 8) * SWPAD + cp] = h;
            Alo[(rl + 8) * SWPAD + cp] = l;
        }
    }
    stage_w(Whs, Wls, wIdxB, tid);
    __syncthreads();

#pragma unroll
    for (int m = 0; m < 2; m++)
#pragma unroll
        for (int n = 0; n < 4; n++)
#pragma unroll
            for (int q = 0; q < 4; q++) acc[m][n][q] = 0.f;

    mlp_mainloop(Ahi, Alo, Whs, Wls, acc, wr, wc, lr, lc);
    __syncthreads();

    // C2 = relu(acc + bB) into SMEM (reuse W buffers), dot with w3
    float* Cs = (float*)Whs;   // [64][132]
#pragma unroll
    for (int m = 0; m < 2; m++) {
        int rl = wr + m * 16 + lr;
#pragma unroll
        for (int n = 0; n < 4; n++) {
            int col = wc + n * 8 + lc * 2;
            float bx = bB[col], by = bB[col + 1];
            float2 o0, o1;
            o0.x = fmaxf(acc[m][n][0] + bx, 0.f);
            o0.y = fmaxf(acc[m][n][1] + by, 0.f);
            o1.x = fmaxf(acc[m][n][2] + bx, 0.f);
            o1.y = fmaxf(acc[m][n][3] + by, 0.f);
            *(float2*)&Cs[rl * 132 + col] = o0;
            *(float2*)&Cs[(rl + 8) * 132 + col] = o1;
        }
    }
    __syncthreads();
    float4 w = *(const float4*)&w3[lane * 4];
    float bias3 = b3[0];
#pragma unroll
    for (int r8 = 0; r8 < 8; r8++) {
        int row = wid * 8 + r8;
        float4 a = *(const float4*)&Cs[row * 132 + lane * 4];
        float s = a.x * w.x + a.y * w.y + a.z * w.z + a.w * w.w;
#pragma unroll
        for (int o = 16; o > 0; o >>= 1)
            s += __shfl_down_sync(0xFFFFFFFFu, s, o);
        if (lane == 0 && row0 + row < M)
            out[row0 + row] = s + bias3;
    }
}

// ---------------- launcher ----------------
extern "C" void kernel_launch(void* const* d_in, const int* in_sizes, int n_in,
                              void* d_out, int out_size) {
    const int*   node_type  = (const int*)  d_in[0];
    const int*   edge_type  = (const int*)  d_in[1];
    const int*   edge_index = (const int*)  d_in[2];
    const float* node_emb   = (const float*)d_in[3];
    const float* edge_emb   = (const float*)d_in[4];
    const float* eps        = (const float*)d_in[5];
    const float* W1         = (const float*)d_in[6];
    const float* b1         = (const float*)d_in[7];
    const float* W2         = (const float*)d_in[8];
    const float* b2         = (const float*)d_in[9];
    const float* gamma      = (const float*)d_in[10];
    const float* beta       = (const float*)d_in[11];
    const float* hW1        = (const float*)d_in[12];
    const float* hb1        = (const float*)d_in[13];
    const float* hW2        = (const float*)d_in[14];
    const float* hb2        = (const float*)d_in[15];
    const float* hW3        = (const float*)d_in[16];
    const float* hb3        = (const float*)d_in[17];
    float* out = (float*)d_out;

    int N = in_sizes[0];
    int E = in_sizes[1];
    int gTiles = (N + 63) / 64;
    int scanBlocks = (N + 1023) / 1024;

    static int smemSet = 0;
    if (!smemSet) {
        cudaFuncSetAttribute(k_fused<0>, cudaFuncAttributeMaxDynamicSharedMemorySize, GEMM_SMEM);
        cudaFuncSetAttribute(k_fused<1>, cudaFuncAttributeMaxDynamicSharedMemorySize, GEMM_SMEM);
        cudaFuncSetAttribute(k_head, cudaFuncAttributeMaxDynamicSharedMemorySize, GEMM_SMEM);
        smemSet = 1;
    }

    // prep: weight split + zero deg/stats/scan-state (runs first)
    k_wsplit<<<(8 * 128 * 64 + 255) / 256, 256>>>(W1, W2, hW1, hW2, N);

    // CSR build: hist -> single-pass lookback scan -> fill
    k_hist<<<(E + 255) / 256, 256>>>(edge_index, E);
    k_scan_lb<<<scanBlocks, 256>>>(N, E);
    k_fill<<<(E + 255) / 256, 256>>>(edge_index, edge_type, node_type, E);

    // fused layers: gather(+embed / +BN-of-prev) -> MLP -> h(+stats). buffers ping-pong.
    k_fused<0><<<gTiles, 256, GEMM_SMEM>>>(0, 0, 0, 1, b1, b2, N,
                                           0, -1, nullptr, nullptr,
                                           edge_emb, eps, 0, node_type, node_emb);
    k_fused<1><<<gTiles, 256, GEMM_SMEM>>>(0, 1, 2, 3, b1 + D, b2 + D, N,
                                           1, 0, gamma, beta,
                                           edge_emb, eps, 1, nullptr, nullptr);
    k_fused<1><<<gTiles, 256, GEMM_SMEM>>>(1, 0, 4, 5, b1 + 2 * D, b2 + 2 * D, N,
                                           2, 1, gamma + D, beta + D,
                                           edge_emb, eps, 2, nullptr, nullptr);
    k_head<<<gTiles, 256, GEMM_SMEM>>>(0, 6, 7, hb1, hb2, N,
                                       2, gamma + 2 * D, beta + 2 * D,
                                       hW3, hb3, out);
}